// round 2
// baseline (speedup 1.0000x reference)
#include <cuda_runtime.h>
#include <math.h>

#define NN 100000
#define NE 1600000
#define FIN 128
#define FH  128
#define NC  16

// ---------------- scratch (device globals; no allocation allowed) ----------
__device__ int   g_is64;
__device__ int   g_count[NN];
__device__ int   g_rowptr[NN + 1];
__device__ int   g_woff[NN];
__device__ int   g_ssrc[NE];
__device__ float g_dis[NN];
__device__ float g_hs1[(size_t)NN * FH];   // dis-scaled x@W1
__device__ float g_a1 [(size_t)NN * FH];   // relu(agg1 + b1)
__device__ float g_hs2[(size_t)NN * NC];   // dis-scaled a1@W2

__device__ __forceinline__ int edge_at(const void* p, long long i, int is64) {
    return is64 ? (int)(((const long long*)p)[i]) : ((const int*)p)[i];
}

// ------------- init: zero histogram + detect int64 vs int32 edge_index -----
__global__ void k_init(const void* __restrict__ e) {
    int i = blockIdx.x * blockDim.x + threadIdx.x;
    if (i < NN) g_count[i] = 0;
    if (i == 0) {
        const int* p = (const int*)e;
        int allz = 1;
        #pragma unroll
        for (int k = 0; k < 16; k++)
            if (p[2 * k + 1] != 0) allz = 0;
        g_is64 = allz;   // indices < 100000 -> if int64, every high word is 0
    }
}

__global__ void k_hist(const void* __restrict__ e) {
    int i = blockIdx.x * blockDim.x + threadIdx.x;
    if (i < NE) {
        int d = edge_at(e, (long long)NE + i, g_is64);
        atomicAdd(&g_count[d], 1);
    }
}

// single-block scan: exclusive prefix of g_count -> g_rowptr
__global__ void k_scan() {
    __shared__ int sw[32];
    int tid = threadIdx.x, lane = tid & 31, w = tid >> 5;
    int offset = 0;
    for (int base = 0; base < NN; base += 1024) {
        int idx = base + tid;
        int v = (idx < NN) ? g_count[idx] : 0;
        int x = v;
        #pragma unroll
        for (int d = 1; d < 32; d <<= 1) {
            int t = __shfl_up_sync(0xffffffffu, x, d);
            if (lane >= d) x += t;
        }
        if (lane == 31) sw[w] = x;
        __syncthreads();
        if (w == 0) {
            int y = sw[lane];
            #pragma unroll
            for (int d = 1; d < 32; d <<= 1) {
                int t = __shfl_up_sync(0xffffffffu, y, d);
                if (lane >= d) y += t;
            }
            sw[lane] = y;
        }
        __syncthreads();
        int wpre = (w > 0) ? sw[w - 1] : 0;
        if (idx < NN) g_rowptr[idx] = offset + (x + wpre) - v;
        offset += sw[31];
        __syncthreads();
    }
    if (tid == 0) g_rowptr[NN] = offset;
}

__global__ void k_prep() {
    int i = blockIdx.x * blockDim.x + threadIdx.x;
    if (i < NN) {
        int r0 = g_rowptr[i], r1 = g_rowptr[i + 1];
        g_dis[i]  = rsqrtf((float)(r1 - r0 + 1));  // +1 self loop
        g_woff[i] = r0;
    }
}

__global__ void k_scatter(const void* __restrict__ e) {
    int i = blockIdx.x * blockDim.x + threadIdx.x;
    if (i < NE) {
        int is64 = g_is64;
        int s = edge_at(e, i, is64);
        int d = edge_at(e, (long long)NE + i, is64);
        int pos = atomicAdd(&g_woff[d], 1);
        g_ssrc[pos] = s;
    }
}

// ---------------- GEMM1: hs1[r] = dis[r] * (x[r] @ W1), 64x128 tile --------
__global__ void k_gemm1(const float* __restrict__ x, const float* __restrict__ W) {
    __shared__ float xs[64][33];     // [row][k], padded
    __shared__ float ws[32][128];    // [k][col]
    int tid = threadIdx.x;
    int tx = tid & 31;               // col group: 4 cols
    int ty = tid >> 5;               // row group: 8 rows
    int blockRow = blockIdx.x * 64;

    float acc[8][4];
    #pragma unroll
    for (int i = 0; i < 8; i++)
        #pragma unroll
        for (int j = 0; j < 4; j++) acc[i][j] = 0.f;

    for (int k0 = 0; k0 < FIN; k0 += 32) {
        #pragma unroll
        for (int i = 0; i < 2; i++) {
            int t = tid + i * 256;           // 0..511
            int r = t >> 3;                  // 0..63
            int kk = (t & 7) * 4;            // 0..28
            int grow = blockRow + r;
            float4 v = make_float4(0.f, 0.f, 0.f, 0.f);
            if (grow < NN) v = *(const float4*)&x[(size_t)grow * FIN + k0 + kk];
            xs[r][kk + 0] = v.x; xs[r][kk + 1] = v.y;
            xs[r][kk + 2] = v.z; xs[r][kk + 3] = v.w;
        }
        #pragma unroll
        for (int i = 0; i < 4; i++) {
            int t = tid + i * 256;           // 0..1023
            int kk = t >> 5;                 // 0..31
            int c = (t & 31) * 4;            // 0..124
            *(float4*)&ws[kk][c] = *(const float4*)&W[(size_t)(k0 + kk) * FH + c];
        }
        __syncthreads();
        #pragma unroll
        for (int k = 0; k < 32; k++) {
            float bfr[4];
            *(float4*)bfr = *(const float4*)&ws[k][tx * 4];
            float afr[8];
            #pragma unroll
            for (int i = 0; i < 8; i++) afr[i] = xs[ty * 8 + i][k];
            #pragma unroll
            for (int i = 0; i < 8; i++)
                #pragma unroll
                for (int j = 0; j < 4; j++)
                    acc[i][j] = fmaf(afr[i], bfr[j], acc[i][j]);
        }
        __syncthreads();
    }
    #pragma unroll
    for (int i = 0; i < 8; i++) {
        int row = blockRow + ty * 8 + i;
        if (row < NN) {
            float dv = g_dis[row];
            float4 o = make_float4(acc[i][0] * dv, acc[i][1] * dv,
                                   acc[i][2] * dv, acc[i][3] * dv);
            *(float4*)&g_hs1[(size_t)row * FH + tx * 4] = o;
        }
    }
}

// ---------------- Agg layer 1: warp per node, lane owns one float4 ---------
__global__ void k_agg1(const float* __restrict__ b1) {
    int warp = threadIdx.x >> 5, lane = threadIdx.x & 31;
    int node = blockIdx.x * 8 + warp;
    if (node >= NN) return;   // warp-uniform
    const float4* hv = (const float4*)g_hs1;
    float4 acc = hv[(size_t)node * 32 + lane];      // self-loop term
    int s0 = g_rowptr[node], s1 = g_rowptr[node + 1];
    for (int base = s0; base < s1; base += 32) {
        int j = base + lane;
        int sidx = (j < s1) ? g_ssrc[j] : 0;
        int cnt = min(32, s1 - base);
        for (int k = 0; k < cnt; k++) {
            int ss = __shfl_sync(0xffffffffu, sidx, k);
            float4 v = hv[(size_t)ss * 32 + lane];
            acc.x += v.x; acc.y += v.y; acc.z += v.z; acc.w += v.w;
        }
    }
    float dv = g_dis[node];
    float4 b = ((const float4*)b1)[lane];
    float4 o;
    o.x = fmaxf(fmaf(acc.x, dv, b.x), 0.f);
    o.y = fmaxf(fmaf(acc.y, dv, b.y), 0.f);
    o.z = fmaxf(fmaf(acc.z, dv, b.z), 0.f);
    o.w = fmaxf(fmaf(acc.w, dv, b.w), 0.f);
    ((float4*)g_a1)[(size_t)node * 32 + lane] = o;
}

// ---------------- GEMM2: hs2[r] = dis[r] * (a1[r] @ W2), 64 nodes/block ----
__global__ void k_gemm2(const float* __restrict__ W2) {
    __shared__ float as[64][132];
    __shared__ float ws2[FH * NC];
    int tid = threadIdx.x;
    int n  = tid >> 2;          // 0..63
    int cg = (tid & 3) * 4;     // 0,4,8,12
    int blockRow = blockIdx.x * 64;

    #pragma unroll
    for (int i = 0; i < 8; i++) {
        int t = tid + i * 256;           // 0..2047
        int row = t >> 5;                // 0..63
        int kk = (t & 31) * 4;           // 0..124
        int grow = blockRow + row;
        float4 v = make_float4(0.f, 0.f, 0.f, 0.f);
        if (grow < NN) v = *(const float4*)&g_a1[(size_t)grow * FH + kk];
        as[row][kk + 0] = v.x; as[row][kk + 1] = v.y;
        as[row][kk + 2] = v.z; as[row][kk + 3] = v.w;
    }
    #pragma unroll
    for (int i = 0; i < 8; i++) {
        int t = tid + i * 256;
        ws2[t] = W2[t];
    }
    __syncthreads();

    float4 acc = make_float4(0.f, 0.f, 0.f, 0.f);
    #pragma unroll 8
    for (int k = 0; k < FH; k++) {
        float av = as[n][k];
        float4 w = *(const float4*)&ws2[k * NC + cg];
        acc.x = fmaf(av, w.x, acc.x);
        acc.y = fmaf(av, w.y, acc.y);
        acc.z = fmaf(av, w.z, acc.z);
        acc.w = fmaf(av, w.w, acc.w);
    }
    int row = blockRow + n;
    if (row < NN) {
        float dv = g_dis[row];
        float4 o = make_float4(acc.x * dv, acc.y * dv, acc.z * dv, acc.w * dv);
        *(float4*)&g_hs2[(size_t)row * NC + cg] = o;
    }
}

// ---------------- Agg layer 2 + bias + log_softmax (quad per node) ---------
__global__ void k_agg2(const float* __restrict__ b2, float* __restrict__ out) {
    int gt = blockIdx.x * blockDim.x + threadIdx.x;
    int node = gt >> 2;
    int q = gt & 3;
    int node_c = (node < NN) ? node : (NN - 1);   // keep all lanes active
    const float4* hv = (const float4*)g_hs2;
    float4 acc = hv[(size_t)node_c * 4 + q];      // self-loop
    int s0 = g_rowptr[node_c], s1 = g_rowptr[node_c + 1];
    for (int j = s0; j < s1; j++) {
        int s = g_ssrc[j];
        float4 v = hv[(size_t)s * 4 + q];
        acc.x += v.x; acc.y += v.y; acc.z += v.z; acc.w += v.w;
    }
    float dv = g_dis[node_c];
    float4 b = ((const float4*)b2)[q];
    float v0 = fmaf(acc.x, dv, b.x);
    float v1 = fmaf(acc.y, dv, b.y);
    float v2 = fmaf(acc.z, dv, b.z);
    float v3 = fmaf(acc.w, dv, b.w);
    float m = fmaxf(fmaxf(v0, v1), fmaxf(v2, v3));
    m = fmaxf(m, __shfl_xor_sync(0xffffffffu, m, 1));
    m = fmaxf(m, __shfl_xor_sync(0xffffffffu, m, 2));
    float e = expf(v0 - m) + expf(v1 - m) + expf(v2 - m) + expf(v3 - m);
    e += __shfl_xor_sync(0xffffffffu, e, 1);
    e += __shfl_xor_sync(0xffffffffu, e, 2);
    float lse = m + logf(e);
    if (node < NN) {
        float4 o = make_float4(v0 - lse, v1 - lse, v2 - lse, v3 - lse);
        ((float4*)out)[(size_t)node * 4 + q] = o;
    }
}

// ---------------- launch --------------------------------------------------
extern "C" void kernel_launch(void* const* d_in, const int* in_sizes, int n_in,
                              void* d_out, int out_size) {
    const float* x  = (const float*)d_in[0];
    const void*  ei = d_in[1];
    const float* W1 = (const float*)d_in[2];
    const float* b1 = (const float*)d_in[3];
    const float* W2 = (const float*)d_in[4];
    const float* b2 = (const float*)d_in[5];
    float* out = (float*)d_out;

    k_init<<<(NN + 255) / 256, 256>>>(ei);
    k_hist<<<(NE + 255) / 256, 256>>>(ei);
    k_scan<<<1, 1024>>>();
    k_prep<<<(NN + 255) / 256, 256>>>();
    k_scatter<<<(NE + 255) / 256, 256>>>(ei);
    k_gemm1<<<(NN + 63) / 64, 256>>>(x, W1);
    k_agg1<<<(NN + 7) / 8, 256>>>(b1);
    k_gemm2<<<(NN + 63) / 64, 256>>>(W2);
    k_agg2<<<(NN * 4 + 255) / 256, 256>>>(b2, out);
}

// round 3
// speedup vs baseline: 1.0164x; 1.0164x over previous
#include <cuda_runtime.h>
#include <math.h>

#define NN 100000
#define NE 1600000
#define FIN 128
#define FH  128
#define NC  16
#define NB  98   // ceil(NN/1024)

// packed fp32x2 helpers (Blackwell FFMA2 path — exact fp32, 2x fma-pipe rate)
#define FMA2(d, a, b) asm("fma.rn.f32x2 %0, %1, %2, %3;" : "=l"(d) : "l"(a), "l"(b), "l"(d))
#define ADD2(d, v)    asm("add.rn.f32x2 %0, %1, %2;"     : "=l"(d) : "l"(d), "l"(v))
#define DUP2(d, f)    asm("mov.b64 %0, {%1, %1};"        : "=l"(d) : "f"(f))
#define UNPK2(lo, hi, v) asm("mov.b64 {%0, %1}, %2;" : "=f"(lo), "=f"(hi) : "l"(v))

// ---------------- scratch (device globals; no allocation allowed) ----------
__device__ int   g_is64;
__device__ int   g_count[NN];
__device__ int   g_rowptr[NN + 1];
__device__ int   g_woff[NN];
__device__ int   g_bsum[NB];
__device__ int   g_boff[NB];
__device__ int   g_ssrc[NE];
__device__ float g_dis[NN];
__device__ float g_hs1[(size_t)NN * FH];   // dis-scaled x@W1
__device__ float g_a1 [(size_t)NN * FH];   // relu(agg1 + b1)
__device__ float g_hs2[(size_t)NN * NC];   // dis-scaled a1@W2

// ------------- init: zero histogram + detect int64 vs int32 edge_index -----
__global__ void k_init(const void* __restrict__ e) {
    int i = blockIdx.x * blockDim.x + threadIdx.x;
    if (i < NN) g_count[i] = 0;
    if (i == 0) {
        const int* p = (const int*)e;
        int allz = 1;
        #pragma unroll
        for (int k = 0; k < 16; k++)
            if (p[2 * k + 1] != 0) allz = 0;
        g_is64 = allz;   // indices < 100000 -> if int64, every high word is 0
    }
}

// ---------------- histogram of dst (2 edges / thread, vector loads) --------
__global__ void k_hist(const void* __restrict__ e) {
    int i = blockIdx.x * blockDim.x + threadIdx.x;
    if (i < NE / 2) {
        if (g_is64) {
            longlong2 d = ((const longlong2*)e)[NE / 2 + i];
            atomicAdd(&g_count[(int)d.x], 1);
            atomicAdd(&g_count[(int)d.y], 1);
        } else {
            int2 d = ((const int2*)e)[NE / 2 + i];
            atomicAdd(&g_count[d.x], 1);
            atomicAdd(&g_count[d.y], 1);
        }
    }
}

// ---------------- multi-block exclusive scan of g_count -> g_rowptr --------
__global__ void k_scanA() {
    __shared__ int sw[32];
    int tid = threadIdx.x, lane = tid & 31, w = tid >> 5;
    int idx = blockIdx.x * 1024 + tid;
    int v = (idx < NN) ? g_count[idx] : 0;
    int x = v;
    #pragma unroll
    for (int d = 1; d < 32; d <<= 1) {
        int t = __shfl_up_sync(0xffffffffu, x, d);
        if (lane >= d) x += t;
    }
    if (lane == 31) sw[w] = x;
    __syncthreads();
    if (w == 0) {
        int y = sw[lane];
        #pragma unroll
        for (int d = 1; d < 32; d <<= 1) {
            int t = __shfl_up_sync(0xffffffffu, y, d);
            if (lane >= d) y += t;
        }
        sw[lane] = y;
    }
    __syncthreads();
    int wpre = (w > 0) ? sw[w - 1] : 0;
    if (idx < NN) g_rowptr[idx] = wpre + x - v;   // exclusive within block
    if (tid == 1023) g_bsum[blockIdx.x] = wpre + x;
}

__global__ void k_scanB() {
    __shared__ int sw[4];
    int tid = threadIdx.x, lane = tid & 31, w = tid >> 5;
    int v = (tid < NB) ? g_bsum[tid] : 0;
    int x = v;
    #pragma unroll
    for (int d = 1; d < 32; d <<= 1) {
        int t = __shfl_up_sync(0xffffffffu, x, d);
        if (lane >= d) x += t;
    }
    if (lane == 31) sw[w] = x;
    __syncthreads();
    int woff = 0;
    for (int i = 0; i < w; i++) woff += sw[i];
    if (tid < NB) g_boff[tid] = woff + x - v;
}

// add block offsets + compute dis/woff (prep folded in)
__global__ void k_scanC() {
    int i = blockIdx.x * blockDim.x + threadIdx.x;
    if (i < NN) {
        int rp = g_rowptr[i] + g_boff[i >> 10];
        g_rowptr[i] = rp;
        g_woff[i]   = rp;
        g_dis[i]    = rsqrtf((float)(g_count[i] + 1));  // +1 self loop
        if (i == 0) g_rowptr[NN] = NE;
    }
}

// ---------------- counting-sort scatter of src by dst ----------------------
__global__ void k_scatter(const void* __restrict__ e) {
    int i = blockIdx.x * blockDim.x + threadIdx.x;
    if (i < NE / 2) {
        int s0, s1, d0, d1;
        if (g_is64) {
            longlong2 s = ((const longlong2*)e)[i];
            longlong2 d = ((const longlong2*)e)[NE / 2 + i];
            s0 = (int)s.x; s1 = (int)s.y; d0 = (int)d.x; d1 = (int)d.y;
        } else {
            int2 s = ((const int2*)e)[i];
            int2 d = ((const int2*)e)[NE / 2 + i];
            s0 = s.x; s1 = s.y; d0 = d.x; d1 = d.y;
        }
        g_ssrc[atomicAdd(&g_woff[d0], 1)] = s0;
        g_ssrc[atomicAdd(&g_woff[d1], 1)] = s1;
    }
}

// ---------------- GEMM1 (f32x2): hs1[r] = dis[r] * (x[r] @ W1) --------------
// 64x128 tile, 256 threads. x packed as row-pairs, W lane-duplicated.
__global__ void k_gemm1(const float* __restrict__ x, const float* __restrict__ W) {
    __shared__ unsigned long long xs2[32][33];   // [k][row-pair], {x[2r][k], x[2r+1][k]}
    __shared__ unsigned long long wd[32][128];   // [k][col], {W,W} duplicated
    int tid = threadIdx.x;
    int tx = tid & 31;               // col group: 4 cols
    int ty = tid >> 5;               // row group: 8 rows = 4 pairs
    int blockRow = blockIdx.x * 64;

    unsigned long long acc2[4][4];   // [row-pair][col] packed fp32x2
    #pragma unroll
    for (int i = 0; i < 4; i++)
        #pragma unroll
        for (int j = 0; j < 4; j++) acc2[i][j] = 0ULL;

    for (int k0 = 0; k0 < FIN; k0 += 32) {
        #pragma unroll
        for (int it = 0; it < 2; it++) {
            int t = tid + it * 256;          // 0..511
            int r = t >> 3;                  // 0..63
            int kk = (t & 7) * 4;            // 0..28
            int grow = blockRow + r;
            float4 v = make_float4(0.f, 0.f, 0.f, 0.f);
            if (grow < NN) v = *(const float4*)&x[(size_t)grow * FIN + k0 + kk];
            int rp = r >> 1, h = r & 1;
            ((float*)&xs2[kk + 0][rp])[h] = v.x;
            ((float*)&xs2[kk + 1][rp])[h] = v.y;
            ((float*)&xs2[kk + 2][rp])[h] = v.z;
            ((float*)&xs2[kk + 3][rp])[h] = v.w;
        }
        #pragma unroll
        for (int it = 0; it < 16; it++) {
            int t = tid + it * 256;          // 0..4095
            int kk = t >> 7;                 // 0..31
            int c = t & 127;
            float wv = W[(size_t)(k0 + kk) * FH + c];
            unsigned long long d;
            DUP2(d, wv);
            wd[kk][c] = d;
        }
        __syncthreads();
        #pragma unroll
        for (int k = 0; k < 32; k++) {
            unsigned long long a01[4];
            #pragma unroll
            for (int i = 0; i < 4; i++) a01[i] = xs2[k][ty * 4 + i];
            ulonglong2 w01 = *(const ulonglong2*)&wd[k][tx * 4];
            ulonglong2 w23 = *(const ulonglong2*)&wd[k][tx * 4 + 2];
            #pragma unroll
            for (int i = 0; i < 4; i++) {
                FMA2(acc2[i][0], a01[i], w01.x);
                FMA2(acc2[i][1], a01[i], w01.y);
                FMA2(acc2[i][2], a01[i], w23.x);
                FMA2(acc2[i][3], a01[i], w23.y);
            }
        }
        __syncthreads();
    }
    #pragma unroll
    for (int i = 0; i < 4; i++) {
        float lo[4], hi[4];
        #pragma unroll
        for (int j = 0; j < 4; j++) UNPK2(lo[j], hi[j], acc2[i][j]);
        int r0 = blockRow + ty * 8 + 2 * i;
        int r1 = r0 + 1;
        if (r0 < NN) {
            float dv = g_dis[r0];
            float4 o = make_float4(lo[0] * dv, lo[1] * dv, lo[2] * dv, lo[3] * dv);
            *(float4*)&g_hs1[(size_t)r0 * FH + tx * 4] = o;
        }
        if (r1 < NN) {
            float dv = g_dis[r1];
            float4 o = make_float4(hi[0] * dv, hi[1] * dv, hi[2] * dv, hi[3] * dv);
            *(float4*)&g_hs1[(size_t)r1 * FH + tx * 4] = o;
        }
    }
}

// ---------------- Agg layer 1: warp per node, lane owns one float4 ---------
__global__ void k_agg1(const float* __restrict__ b1) {
    int warp = threadIdx.x >> 5, lane = threadIdx.x & 31;
    int node = blockIdx.x * 8 + warp;
    if (node >= NN) return;   // warp-uniform
    const ulonglong2* hv = (const ulonglong2*)g_hs1;
    ulonglong2 self = hv[(size_t)node * 32 + lane];
    unsigned long long aA0 = self.x, aA1 = self.y;   // chain A seeded w/ self-loop
    unsigned long long aB0 = 0ULL, aB1 = 0ULL;
    int s0 = g_rowptr[node], s1 = g_rowptr[node + 1];
    for (int base = s0; base < s1; base += 32) {
        int j = base + lane;
        int sidx = (j < s1) ? g_ssrc[j] : 0;
        int cnt = min(32, s1 - base);
        int k = 0;
        for (; k + 1 < cnt; k += 2) {
            int ssA = __shfl_sync(0xffffffffu, sidx, k);
            int ssB = __shfl_sync(0xffffffffu, sidx, k + 1);
            ulonglong2 vA = hv[(size_t)ssA * 32 + lane];
            ulonglong2 vB = hv[(size_t)ssB * 32 + lane];
            ADD2(aA0, vA.x); ADD2(aA1, vA.y);
            ADD2(aB0, vB.x); ADD2(aB1, vB.y);
        }
        if (k < cnt) {
            int ss = __shfl_sync(0xffffffffu, sidx, k);
            ulonglong2 v = hv[(size_t)ss * 32 + lane];
            ADD2(aA0, v.x); ADD2(aA1, v.y);
        }
    }
    ADD2(aA0, aB0); ADD2(aA1, aB1);
    float a0, a1, a2, a3;
    UNPK2(a0, a1, aA0); UNPK2(a2, a3, aA1);
    float dv = g_dis[node];
    float4 b = ((const float4*)b1)[lane];
    float4 o;
    o.x = fmaxf(fmaf(a0, dv, b.x), 0.f);
    o.y = fmaxf(fmaf(a1, dv, b.y), 0.f);
    o.z = fmaxf(fmaf(a2, dv, b.z), 0.f);
    o.w = fmaxf(fmaf(a3, dv, b.w), 0.f);
    ((float4*)g_a1)[(size_t)node * 32 + lane] = o;
}

// ---------------- GEMM2 (f32x2): hs2[r] = dis[r] * (a1[r] @ W2) -------------
__global__ void k_gemm2(const float* __restrict__ W2) {
    __shared__ float as[64][132];
    __shared__ float ws2[FH * NC];
    int tid = threadIdx.x;
    int n  = tid >> 2;          // 0..63
    int cg = (tid & 3) * 4;     // 0,4,8,12
    int blockRow = blockIdx.x * 64;

    #pragma unroll
    for (int i = 0; i < 8; i++) {
        int t = tid + i * 256;           // 0..2047
        int row = t >> 5;                // 0..63
        int kk = (t & 31) * 4;           // 0..124
        int grow = blockRow + row;
        float4 v = make_float4(0.f, 0.f, 0.f, 0.f);
        if (grow < NN) v = *(const float4*)&g_a1[(size_t)grow * FH + kk];
        as[row][kk + 0] = v.x; as[row][kk + 1] = v.y;
        as[row][kk + 2] = v.z; as[row][kk + 3] = v.w;
    }
    #pragma unroll
    for (int i = 0; i < 8; i++) {
        int t = tid + i * 256;
        ws2[t] = W2[t];
    }
    __syncthreads();

    unsigned long long acc2[2] = {0ULL, 0ULL};   // cols (cg,cg+1),(cg+2,cg+3)
    #pragma unroll 8
    for (int k = 0; k < FH; k++) {
        float av = as[n][k];
        unsigned long long a2;
        DUP2(a2, av);
        ulonglong2 wv = *(const ulonglong2*)&ws2[k * NC + cg];
        FMA2(acc2[0], a2, wv.x);
        FMA2(acc2[1], a2, wv.y);
    }
    int row = blockRow + n;
    if (row < NN) {
        float l0, h0, l1, h1;
        UNPK2(l0, h0, acc2[0]); UNPK2(l1, h1, acc2[1]);
        float dv = g_dis[row];
        float4 o = make_float4(l0 * dv, h0 * dv, l1 * dv, h1 * dv);
        *(float4*)&g_hs2[(size_t)row * NC + cg] = o;
    }
}

// ---------------- Agg layer 2 + bias + log_softmax (quad per node) ---------
__global__ void k_agg2(const float* __restrict__ b2, float* __restrict__ out) {
    int gt = blockIdx.x * blockDim.x + threadIdx.x;
    int node = gt >> 2;
    int q = gt & 3;
    int node_c = (node < NN) ? node : (NN - 1);   // keep all lanes active
    const ulonglong2* hv = (const ulonglong2*)g_hs2;
    ulonglong2 self = hv[(size_t)node_c * 4 + q];
    unsigned long long aA0 = self.x, aA1 = self.y;
    unsigned long long aB0 = 0ULL, aB1 = 0ULL;
    int s0 = g_rowptr[node_c], s1 = g_rowptr[node_c + 1];
    int j = s0;
    for (; j + 1 < s1; j += 2) {
        int sA = g_ssrc[j], sB = g_ssrc[j + 1];
        ulonglong2 vA = hv[(size_t)sA * 4 + q];
        ulonglong2 vB = hv[(size_t)sB * 4 + q];
        ADD2(aA0, vA.x); ADD2(aA1, vA.y);
        ADD2(aB0, vB.x); ADD2(aB1, vB.y);
    }
    if (j < s1) {
        int s = g_ssrc[j];
        ulonglong2 v = hv[(size_t)s * 4 + q];
        ADD2(aA0, v.x); ADD2(aA1, v.y);
    }
    ADD2(aA0, aB0); ADD2(aA1, aB1);
    float a0, a1, a2, a3;
    UNPK2(a0, a1, aA0); UNPK2(a2, a3, aA1);
    float dv = g_dis[node_c];
    float4 b = ((const float4*)b2)[q];
    float v0 = fmaf(a0, dv, b.x);
    float v1 = fmaf(a1, dv, b.y);
    float v2 = fmaf(a2, dv, b.z);
    float v3 = fmaf(a3, dv, b.w);
    float m = fmaxf(fmaxf(v0, v1), fmaxf(v2, v3));
    m = fmaxf(m, __shfl_xor_sync(0xffffffffu, m, 1));
    m = fmaxf(m, __shfl_xor_sync(0xffffffffu, m, 2));
    float e = expf(v0 - m) + expf(v1 - m) + expf(v2 - m) + expf(v3 - m);
    e += __shfl_xor_sync(0xffffffffu, e, 1);
    e += __shfl_xor_sync(0xffffffffu, e, 2);
    float lse = m + logf(e);
    if (node < NN) {
        float4 o = make_float4(v0 - lse, v1 - lse, v2 - lse, v3 - lse);
        ((float4*)out)[(size_t)node * 4 + q] = o;
    }
}

// ---------------- launch --------------------------------------------------
extern "C" void kernel_launch(void* const* d_in, const int* in_sizes, int n_in,
                              void* d_out, int out_size) {
    const float* x  = (const float*)d_in[0];
    const void*  ei = d_in[1];
    const float* W1 = (const float*)d_in[2];
    const float* b1 = (const float*)d_in[3];
    const float* W2 = (const float*)d_in[4];
    const float* b2 = (const float*)d_in[5];
    float* out = (float*)d_out;

    k_init<<<(NN + 255) / 256, 256>>>(ei);
    k_hist<<<(NE / 2 + 255) / 256, 256>>>(ei);
    k_scanA<<<NB, 1024>>>();
    k_scanB<<<1, 128>>>();
    k_scanC<<<(NN + 255) / 256, 256>>>();
    k_scatter<<<(NE / 2 + 255) / 256, 256>>>(ei);
    k_gemm1<<<(NN + 63) / 64, 256>>>(x, W1);
    k_agg1<<<(NN + 7) / 8, 256>>>(b1);
    k_gemm2<<<(NN + 63) / 64, 256>>>(W2);
    k_agg2<<<(NN * 4 + 255) / 256, 256>>>(b2, out);
}

// round 4
// speedup vs baseline: 1.1528x; 1.1342x over previous
#include <cuda_runtime.h>
#include <math.h>

#define NN 100000
#define NE 1600000
#define FIN 128
#define FH  128
#define NC  16
#define NB  98   // ceil(NN/1024)

typedef unsigned long long u64;

// packed fp32x2 helpers (Blackwell FFMA2 path — exact fp32, 2x fma-pipe rate)
#define FMA2(d, a, b) asm("fma.rn.f32x2 %0, %1, %2, %3;" : "=l"(d) : "l"(a), "l"(b), "l"(d))
#define ADD2(d, v)    asm("add.rn.f32x2 %0, %1, %2;"     : "=l"(d) : "l"(d), "l"(v))
#define DUP2(d, f)    asm("mov.b64 %0, {%1, %1};"        : "=l"(d) : "f"(f))
#define UNPK2(lo, hi, v) asm("mov.b64 {%0, %1}, %2;" : "=f"(lo), "=f"(hi) : "l"(v))

// ---------------- scratch (device globals; no allocation allowed) ----------
__device__ int   g_is64;
__device__ int   g_count[NN];
__device__ int   g_rowptr[NN + 1];
__device__ int   g_woff[NN];
__device__ int   g_bsum[NB];
__device__ int   g_boff[NB];
__device__ int   g_ssrc[NE];
__device__ float g_dis[NN];
__device__ float g_hs1[(size_t)NN * FH];   // UNSCALED x@W1
__device__ float g_a1 [(size_t)NN * FH];   // relu(agg1 + b1)
__device__ float g_hs2[(size_t)NN * NC];   // dis-scaled a1@W2

// ------------- init: zero histogram + detect int64 vs int32 edge_index -----
__global__ void k_init(const void* __restrict__ e) {
    int i = blockIdx.x * blockDim.x + threadIdx.x;
    if (i < NN) g_count[i] = 0;
    if (i == 0) {
        const int* p = (const int*)e;
        int allz = 1;
        #pragma unroll
        for (int k = 0; k < 16; k++)
            if (p[2 * k + 1] != 0) allz = 0;
        g_is64 = allz;   // indices < 100000 -> if int64, every high word is 0
    }
}

// ---------------- histogram of dst (2 edges / thread, vector loads) --------
__global__ void k_hist(const void* __restrict__ e) {
    int i = blockIdx.x * blockDim.x + threadIdx.x;
    if (i < NE / 2) {
        if (g_is64) {
            longlong2 d = ((const longlong2*)e)[NE / 2 + i];
            atomicAdd(&g_count[(int)d.x], 1);
            atomicAdd(&g_count[(int)d.y], 1);
        } else {
            int2 d = ((const int2*)e)[NE / 2 + i];
            atomicAdd(&g_count[d.x], 1);
            atomicAdd(&g_count[d.y], 1);
        }
    }
}

// ---------------- multi-block exclusive scan of g_count -> g_rowptr --------
__global__ void k_scanA() {
    __shared__ int sw[32];
    int tid = threadIdx.x, lane = tid & 31, w = tid >> 5;
    int idx = blockIdx.x * 1024 + tid;
    int v = (idx < NN) ? g_count[idx] : 0;
    int x = v;
    #pragma unroll
    for (int d = 1; d < 32; d <<= 1) {
        int t = __shfl_up_sync(0xffffffffu, x, d);
        if (lane >= d) x += t;
    }
    if (lane == 31) sw[w] = x;
    __syncthreads();
    if (w == 0) {
        int y = sw[lane];
        #pragma unroll
        for (int d = 1; d < 32; d <<= 1) {
            int t = __shfl_up_sync(0xffffffffu, y, d);
            if (lane >= d) y += t;
        }
        sw[lane] = y;
    }
    __syncthreads();
    int wpre = (w > 0) ? sw[w - 1] : 0;
    if (idx < NN) g_rowptr[idx] = wpre + x - v;   // exclusive within block
    if (tid == 1023) g_bsum[blockIdx.x] = wpre + x;
}

__global__ void k_scanB() {
    __shared__ int sw[4];
    int tid = threadIdx.x, lane = tid & 31, w = tid >> 5;
    int v = (tid < NB) ? g_bsum[tid] : 0;
    int x = v;
    #pragma unroll
    for (int d = 1; d < 32; d <<= 1) {
        int t = __shfl_up_sync(0xffffffffu, x, d);
        if (lane >= d) x += t;
    }
    if (lane == 31) sw[w] = x;
    __syncthreads();
    int woff = 0;
    for (int i = 0; i < w; i++) woff += sw[i];
    if (tid < NB) g_boff[tid] = woff + x - v;
}

// add block offsets + compute dis/woff (prep folded in)
__global__ void k_scanC() {
    int i = blockIdx.x * blockDim.x + threadIdx.x;
    if (i < NN) {
        int rp = g_rowptr[i] + g_boff[i >> 10];
        g_rowptr[i] = rp;
        g_woff[i]   = rp;
        g_dis[i]    = rsqrtf((float)(g_count[i] + 1));  // +1 self loop
        if (i == 0) g_rowptr[NN] = NE;
    }
}

// ---------------- counting-sort scatter of src by dst ----------------------
__global__ void k_scatter(const void* __restrict__ e) {
    int i = blockIdx.x * blockDim.x + threadIdx.x;
    if (i < NE / 2) {
        int s0, s1, d0, d1;
        if (g_is64) {
            longlong2 s = ((const longlong2*)e)[i];
            longlong2 d = ((const longlong2*)e)[NE / 2 + i];
            s0 = (int)s.x; s1 = (int)s.y; d0 = (int)d.x; d1 = (int)d.y;
        } else {
            int2 s = ((const int2*)e)[i];
            int2 d = ((const int2*)e)[NE / 2 + i];
            s0 = s.x; s1 = s.y; d0 = d.x; d1 = d.y;
        }
        g_ssrc[atomicAdd(&g_woff[d0], 1)] = s0;
        g_ssrc[atomicAdd(&g_woff[d1], 1)] = s1;
    }
}

// ------ GEMM1 (f32x2): hs1 = x @ W1 (UNSCALED), 128x128 tile, 256 thr ------
// thread tile: 4 row-pairs x 8 cols (stride-16 cols, conflict-free LDS.64)
__global__ void __launch_bounds__(256) k_gemm1(const float* __restrict__ x,
                                               const float* __restrict__ W) {
    __shared__ u64 xs2[32][65];    // [k][row-pair] {x[2p][k], x[2p+1][k]}
    __shared__ u64 wd[32][129];    // [k][col] {W,W} duplicated
    int tid = threadIdx.x;
    int tx = tid & 15;             // col set: {tx + 16j}
    int ty = tid >> 4;             // pair set: ty*4 .. ty*4+3
    int blockRow = blockIdx.x * 128;

    u64 acc[4][8];
    #pragma unroll
    for (int i = 0; i < 4; i++)
        #pragma unroll
        for (int j = 0; j < 8; j++) acc[i][j] = 0ULL;

    for (int k0 = 0; k0 < FIN; k0 += 32) {
        #pragma unroll
        for (int it = 0; it < 4; it++) {
            int t = tid + it * 256;          // 0..1023
            int r = t >> 3;                  // 0..127
            int kk = (t & 7) * 4;            // 0..28
            int grow = blockRow + r;
            float4 v = make_float4(0.f, 0.f, 0.f, 0.f);
            if (grow < NN) v = *(const float4*)&x[(size_t)grow * FIN + k0 + kk];
            int rp = r >> 1, h = r & 1;
            ((float*)&xs2[kk + 0][rp])[h] = v.x;
            ((float*)&xs2[kk + 1][rp])[h] = v.y;
            ((float*)&xs2[kk + 2][rp])[h] = v.z;
            ((float*)&xs2[kk + 3][rp])[h] = v.w;
        }
        #pragma unroll
        for (int it = 0; it < 16; it++) {
            int t = tid + it * 256;          // 0..4095
            int kk = t >> 7;                 // 0..31
            int c = t & 127;
            float wv = W[(size_t)(k0 + kk) * FH + c];
            u64 d;
            DUP2(d, wv);
            wd[kk][c] = d;
        }
        __syncthreads();
        #pragma unroll
        for (int k = 0; k < 32; k++) {
            u64 a[4];
            #pragma unroll
            for (int i = 0; i < 4; i++) a[i] = xs2[k][ty * 4 + i];
            u64 w[8];
            #pragma unroll
            for (int j = 0; j < 8; j++) w[j] = wd[k][tx + 16 * j];
            #pragma unroll
            for (int i = 0; i < 4; i++)
                #pragma unroll
                for (int j = 0; j < 8; j++)
                    FMA2(acc[i][j], a[i], w[j]);
        }
        __syncthreads();
    }
    #pragma unroll
    for (int i = 0; i < 4; i++) {
        int r0 = blockRow + (ty * 4 + i) * 2;
        int r1 = r0 + 1;
        #pragma unroll
        for (int j = 0; j < 8; j++) {
            float lo, hi;
            UNPK2(lo, hi, acc[i][j]);
            int c = tx + 16 * j;
            if (r0 < NN) g_hs1[(size_t)r0 * FH + c] = lo;
            if (r1 < NN) g_hs1[(size_t)r1 * FH + c] = hi;
        }
    }
}

// ------ Agg layer 1: warp per node, lane owns one float4; dis applied here -
__global__ void k_agg1(const float* __restrict__ b1) {
    int warp = threadIdx.x >> 5, lane = threadIdx.x & 31;
    int node = blockIdx.x * 8 + warp;
    if (node >= NN) return;   // warp-uniform
    const ulonglong2* hv = (const ulonglong2*)g_hs1;
    float dnode = g_dis[node];
    u64 dd;
    DUP2(dd, dnode);
    ulonglong2 self = hv[(size_t)node * 32 + lane];
    u64 aA0 = 0ULL, aA1 = 0ULL, aB0 = 0ULL, aB1 = 0ULL;
    FMA2(aA0, self.x, dd);           // self-loop: dis_i * hs_i
    FMA2(aA1, self.y, dd);
    int s0 = g_rowptr[node], s1 = g_rowptr[node + 1];
    for (int base = s0; base < s1; base += 32) {
        int j = base + lane;
        int sidx = (j < s1) ? __ldcs(&g_ssrc[j]) : 0;
        int cnt = min(32, s1 - base);
        int k = 0;
        for (; k + 1 < cnt; k += 2) {
            int ssA = __shfl_sync(0xffffffffu, sidx, k);
            int ssB = __shfl_sync(0xffffffffu, sidx, k + 1);
            float dA = g_dis[ssA], dB = g_dis[ssB];
            u64 ddA, ddB;
            DUP2(ddA, dA); DUP2(ddB, dB);
            ulonglong2 vA = hv[(size_t)ssA * 32 + lane];
            ulonglong2 vB = hv[(size_t)ssB * 32 + lane];
            FMA2(aA0, vA.x, ddA); FMA2(aA1, vA.y, ddA);
            FMA2(aB0, vB.x, ddB); FMA2(aB1, vB.y, ddB);
        }
        if (k < cnt) {
            int ss = __shfl_sync(0xffffffffu, sidx, k);
            float dC = g_dis[ss];
            u64 ddC;
            DUP2(ddC, dC);
            ulonglong2 v = hv[(size_t)ss * 32 + lane];
            FMA2(aA0, v.x, ddC); FMA2(aA1, v.y, ddC);
        }
    }
    ADD2(aA0, aB0); ADD2(aA1, aB1);
    float a0, a1, a2, a3;
    UNPK2(a0, a1, aA0); UNPK2(a2, a3, aA1);
    float4 b = ((const float4*)b1)[lane];
    float4 o;
    o.x = fmaxf(fmaf(a0, dnode, b.x), 0.f);
    o.y = fmaxf(fmaf(a1, dnode, b.y), 0.f);
    o.z = fmaxf(fmaf(a2, dnode, b.z), 0.f);
    o.w = fmaxf(fmaf(a3, dnode, b.w), 0.f);
    ((float4*)g_a1)[(size_t)node * 32 + lane] = o;
}

// ---------------- GEMM2 (f32x2): hs2[r] = dis[r] * (a1[r] @ W2) -------------
__global__ void k_gemm2(const float* __restrict__ W2) {
    __shared__ float as[64][132];
    __shared__ float ws2[FH * NC];
    int tid = threadIdx.x;
    int n  = tid >> 2;          // 0..63
    int cg = (tid & 3) * 4;     // 0,4,8,12
    int blockRow = blockIdx.x * 64;

    #pragma unroll
    for (int i = 0; i < 8; i++) {
        int t = tid + i * 256;           // 0..2047
        int row = t >> 5;                // 0..63
        int kk = (t & 31) * 4;           // 0..124
        int grow = blockRow + row;
        float4 v = make_float4(0.f, 0.f, 0.f, 0.f);
        if (grow < NN) v = *(const float4*)&g_a1[(size_t)grow * FH + kk];
        as[row][kk + 0] = v.x; as[row][kk + 1] = v.y;
        as[row][kk + 2] = v.z; as[row][kk + 3] = v.w;
    }
    #pragma unroll
    for (int i = 0; i < 8; i++) {
        int t = tid + i * 256;
        ws2[t] = W2[t];
    }
    __syncthreads();

    u64 acc2[2] = {0ULL, 0ULL};   // cols (cg,cg+1),(cg+2,cg+3)
    #pragma unroll 8
    for (int k = 0; k < FH; k++) {
        float av = as[n][k];
        u64 a2;
        DUP2(a2, av);
        ulonglong2 wv = *(const ulonglong2*)&ws2[k * NC + cg];
        FMA2(acc2[0], a2, wv.x);
        FMA2(acc2[1], a2, wv.y);
    }
    int row = blockRow + n;
    if (row < NN) {
        float l0, h0, l1, h1;
        UNPK2(l0, h0, acc2[0]); UNPK2(l1, h1, acc2[1]);
        float dv = g_dis[row];
        float4 o = make_float4(l0 * dv, h0 * dv, l1 * dv, h1 * dv);
        *(float4*)&g_hs2[(size_t)row * NC + cg] = o;
    }
}

// ---------------- Agg layer 2 + bias + log_softmax (quad per node) ---------
__global__ void k_agg2(const float* __restrict__ b2, float* __restrict__ out) {
    int gt = blockIdx.x * blockDim.x + threadIdx.x;
    int node = gt >> 2;
    int q = gt & 3;
    int node_c = (node < NN) ? node : (NN - 1);   // keep all lanes active
    const ulonglong2* hv = (const ulonglong2*)g_hs2;
    ulonglong2 self = hv[(size_t)node_c * 4 + q];
    u64 aA0 = self.x, aA1 = self.y;
    u64 aB0 = 0ULL, aB1 = 0ULL;
    int s0 = g_rowptr[node_c], s1 = g_rowptr[node_c + 1];
    int j = s0;
    for (; j + 1 < s1; j += 2) {
        int sA = __ldcs(&g_ssrc[j]), sB = __ldcs(&g_ssrc[j + 1]);
        ulonglong2 vA = hv[(size_t)sA * 4 + q];
        ulonglong2 vB = hv[(size_t)sB * 4 + q];
        ADD2(aA0, vA.x); ADD2(aA1, vA.y);
        ADD2(aB0, vB.x); ADD2(aB1, vB.y);
    }
    if (j < s1) {
        int s = __ldcs(&g_ssrc[j]);
        ulonglong2 v = hv[(size_t)s * 4 + q];
        ADD2(aA0, v.x); ADD2(aA1, v.y);
    }
    ADD2(aA0, aB0); ADD2(aA1, aB1);
    float a0, a1, a2, a3;
    UNPK2(a0, a1, aA0); UNPK2(a2, a3, aA1);
    float dv = g_dis[node_c];
    float4 b = ((const float4*)b2)[q];
    float v0 = fmaf(a0, dv, b.x);
    float v1 = fmaf(a1, dv, b.y);
    float v2 = fmaf(a2, dv, b.z);
    float v3 = fmaf(a3, dv, b.w);
    float m = fmaxf(fmaxf(v0, v1), fmaxf(v2, v3));
    m = fmaxf(m, __shfl_xor_sync(0xffffffffu, m, 1));
    m = fmaxf(m, __shfl_xor_sync(0xffffffffu, m, 2));
    float e = expf(v0 - m) + expf(v1 - m) + expf(v2 - m) + expf(v3 - m);
    e += __shfl_xor_sync(0xffffffffu, e, 1);
    e += __shfl_xor_sync(0xffffffffu, e, 2);
    float lse = m + logf(e);
    if (node < NN) {
        float4 o = make_float4(v0 - lse, v1 - lse, v2 - lse, v3 - lse);
        ((float4*)out)[(size_t)node * 4 + q] = o;
    }
}

// ---------------- launch (gemm1 moved to slot 3 for the ncu window) --------
extern "C" void kernel_launch(void* const* d_in, const int* in_sizes, int n_in,
                              void* d_out, int out_size) {
    const float* x  = (const float*)d_in[0];
    const void*  ei = d_in[1];
    const float* W1 = (const float*)d_in[2];
    const float* b1 = (const float*)d_in[3];
    const float* W2 = (const float*)d_in[4];
    const float* b2 = (const float*)d_in[5];
    float* out = (float*)d_out;

    k_init<<<(NN + 255) / 256, 256>>>(ei);
    k_hist<<<(NE / 2 + 255) / 256, 256>>>(ei);
    k_scanA<<<NB, 1024>>>();
    k_gemm1<<<(NN + 127) / 128, 256>>>(x, W1);   // slot 3 -> gets profiled
    k_scanB<<<1, 128>>>();
    k_scanC<<<(NN + 255) / 256, 256>>>();
    k_scatter<<<(NE / 2 + 255) / 256, 256>>>(ei);
    k_agg1<<<(NN + 7) / 8, 256>>>(b1);
    k_gemm2<<<(NN + 63) / 64, 256>>>(W2);
    k_agg2<<<(NN * 4 + 255) / 256, 256>>>(b2, out);
}

// round 5
// speedup vs baseline: 1.2955x; 1.1239x over previous
#include <cuda_runtime.h>
#include <math.h>

#define NN 100000
#define NE 1600000
#define FIN 128
#define FH  128
#define NC  16
#define NB  98   // ceil(NN/1024)

typedef unsigned long long u64;

// packed fp32x2 helpers (Blackwell FFMA2 path — exact fp32, 2x fma-pipe rate)
#define FMA2(d, a, b) asm("fma.rn.f32x2 %0, %1, %2, %3;" : "=l"(d) : "l"(a), "l"(b), "l"(d))
#define ADD2(d, v)    asm("add.rn.f32x2 %0, %1, %2;"     : "=l"(d) : "l"(d), "l"(v))
#define DUP2(d, f)    asm("mov.b64 %0, {%1, %1};"        : "=l"(d) : "f"(f))
#define UNPK2(lo, hi, v) asm("mov.b64 {%0, %1}, %2;" : "=f"(lo), "=f"(hi) : "l"(v))

// ---------------- scratch (device globals; no allocation allowed) ----------
__device__ int   g_is64;
__device__ int   g_count[NN];
__device__ int   g_rowptr[NN + 1];
__device__ int   g_woff[NN];
__device__ int   g_bsum[NB];
__device__ int   g_boff[NB];
__device__ int   g_ssrc[NE];
__device__ float g_dis[NN];
__device__ float g_hs1[(size_t)NN * FH];   // UNSCALED x@W1
__device__ float g_a1 [(size_t)NN * FH];   // relu(agg1 + b1)
__device__ float g_hs2[(size_t)NN * NC];   // dis-scaled a1@W2

// ------------- init: zero histogram + detect int64 vs int32 edge_index -----
__global__ void k_init(const void* __restrict__ e) {
    int i = blockIdx.x * blockDim.x + threadIdx.x;
    if (i < NN) g_count[i] = 0;
    if (i == 0) {
        const int* p = (const int*)e;
        int allz = 1;
        #pragma unroll
        for (int k = 0; k < 16; k++)
            if (p[2 * k + 1] != 0) allz = 0;
        g_is64 = allz;   // indices < 100000 -> if int64, every high word is 0
    }
}

// ---------------- histogram of dst (2 edges / thread, vector loads) --------
__global__ void k_hist(const void* __restrict__ e) {
    int i = blockIdx.x * blockDim.x + threadIdx.x;
    if (i < NE / 2) {
        if (g_is64) {
            longlong2 d = ((const longlong2*)e)[NE / 2 + i];
            atomicAdd(&g_count[(int)d.x], 1);
            atomicAdd(&g_count[(int)d.y], 1);
        } else {
            int2 d = ((const int2*)e)[NE / 2 + i];
            atomicAdd(&g_count[d.x], 1);
            atomicAdd(&g_count[d.y], 1);
        }
    }
}

// ---------------- multi-block exclusive scan of g_count -> g_rowptr --------
__global__ void k_scanA() {
    __shared__ int sw[32];
    int tid = threadIdx.x, lane = tid & 31, w = tid >> 5;
    int idx = blockIdx.x * 1024 + tid;
    int v = (idx < NN) ? g_count[idx] : 0;
    int x = v;
    #pragma unroll
    for (int d = 1; d < 32; d <<= 1) {
        int t = __shfl_up_sync(0xffffffffu, x, d);
        if (lane >= d) x += t;
    }
    if (lane == 31) sw[w] = x;
    __syncthreads();
    if (w == 0) {
        int y = sw[lane];
        #pragma unroll
        for (int d = 1; d < 32; d <<= 1) {
            int t = __shfl_up_sync(0xffffffffu, y, d);
            if (lane >= d) y += t;
        }
        sw[lane] = y;
    }
    __syncthreads();
    int wpre = (w > 0) ? sw[w - 1] : 0;
    if (idx < NN) g_rowptr[idx] = wpre + x - v;   // exclusive within block
    if (tid == 1023) g_bsum[blockIdx.x] = wpre + x;
}

__global__ void k_scanB() {
    __shared__ int sw[4];
    int tid = threadIdx.x, lane = tid & 31, w = tid >> 5;
    int v = (tid < NB) ? g_bsum[tid] : 0;
    int x = v;
    #pragma unroll
    for (int d = 1; d < 32; d <<= 1) {
        int t = __shfl_up_sync(0xffffffffu, x, d);
        if (lane >= d) x += t;
    }
    if (lane == 31) sw[w] = x;
    __syncthreads();
    int woff = 0;
    for (int i = 0; i < w; i++) woff += sw[i];
    if (tid < NB) g_boff[tid] = woff + x - v;
}

// add block offsets + compute dis/woff (prep folded in)
__global__ void k_scanC() {
    int i = blockIdx.x * blockDim.x + threadIdx.x;
    if (i < NN) {
        int rp = g_rowptr[i] + g_boff[i >> 10];
        g_rowptr[i] = rp;
        g_woff[i]   = rp;
        g_dis[i]    = rsqrtf((float)(g_count[i] + 1));  // +1 self loop
        if (i == 0) g_rowptr[NN] = NE;
    }
}

// ---------------- counting-sort scatter of src by dst ----------------------
__global__ void k_scatter(const void* __restrict__ e) {
    int i = blockIdx.x * blockDim.x + threadIdx.x;
    if (i < NE / 2) {
        int s0, s1, d0, d1;
        if (g_is64) {
            longlong2 s = ((const longlong2*)e)[i];
            longlong2 d = ((const longlong2*)e)[NE / 2 + i];
            s0 = (int)s.x; s1 = (int)s.y; d0 = (int)d.x; d1 = (int)d.y;
        } else {
            int2 s = ((const int2*)e)[i];
            int2 d = ((const int2*)e)[NE / 2 + i];
            s0 = s.x; s1 = s.y; d0 = d.x; d1 = d.y;
        }
        g_ssrc[atomicAdd(&g_woff[d0], 1)] = s0;
        g_ssrc[atomicAdd(&g_woff[d1], 1)] = s1;
    }
}

// ------ GEMM1 (f32x2): hs1 = x @ W1 (UNSCALED), 128x128 tile, 256 thr ------
// thread tile: 8 rows (4 f32x2 pairs) x 8 cols (stride-16).
// W read as scalar LDS.32 + in-register DUP2 (no duplicated smem array).
__global__ void __launch_bounds__(256, 2) k_gemm1(const float* __restrict__ x,
                                                  const float* __restrict__ W) {
    __shared__ u64   xs2[32][65];    // [k][row-pair] {x[2p][k], x[2p+1][k]}
    __shared__ float ws [32][132];   // [k][col]
    int tid = threadIdx.x;
    int tx = tid & 15;               // col set: {tx + 16j}, j=0..7
    int ty = tid >> 4;               // row pairs: ty*4 .. ty*4+3  (8 rows)
    int blockRow = blockIdx.x * 128;

    u64 acc[4][8];
    #pragma unroll
    for (int i = 0; i < 4; i++)
        #pragma unroll
        for (int j = 0; j < 8; j++) acc[i][j] = 0ULL;

    for (int k0 = 0; k0 < FIN; k0 += 32) {
        #pragma unroll
        for (int it = 0; it < 4; it++) {
            int t = tid + it * 256;          // 0..1023
            int r = t >> 3;                  // 0..127
            int kk = (t & 7) * 4;            // 0..28
            int grow = blockRow + r;
            float4 v = make_float4(0.f, 0.f, 0.f, 0.f);
            if (grow < NN) v = *(const float4*)&x[(size_t)grow * FIN + k0 + kk];
            int rp = r >> 1, h = r & 1;
            ((float*)&xs2[kk + 0][rp])[h] = v.x;
            ((float*)&xs2[kk + 1][rp])[h] = v.y;
            ((float*)&xs2[kk + 2][rp])[h] = v.z;
            ((float*)&xs2[kk + 3][rp])[h] = v.w;
        }
        #pragma unroll
        for (int it = 0; it < 4; it++) {
            int t = tid + it * 256;          // 0..1023
            int kk = t >> 5;                 // 0..31
            int c = (t & 31) * 4;            // 0..124
            *(float4*)&ws[kk][c] = *(const float4*)&W[(size_t)(k0 + kk) * FH + c];
        }
        __syncthreads();
        #pragma unroll 8
        for (int k = 0; k < 32; k++) {
            u64 a[4];
            #pragma unroll
            for (int i = 0; i < 4; i++) a[i] = xs2[k][ty * 4 + i];
            u64 w[8];
            #pragma unroll
            for (int j = 0; j < 8; j++) {
                float wv = ws[k][tx + 16 * j];
                DUP2(w[j], wv);
            }
            #pragma unroll
            for (int i = 0; i < 4; i++)
                #pragma unroll
                for (int j = 0; j < 8; j++)
                    FMA2(acc[i][j], a[i], w[j]);
        }
        __syncthreads();
    }
    #pragma unroll
    for (int i = 0; i < 4; i++) {
        int r0 = blockRow + (ty * 4 + i) * 2;
        int r1 = r0 + 1;
        #pragma unroll
        for (int j = 0; j < 8; j++) {
            float lo, hi;
            UNPK2(lo, hi, acc[i][j]);
            int c = tx + 16 * j;
            if (r0 < NN) g_hs1[(size_t)r0 * FH + c] = lo;
            if (r1 < NN) g_hs1[(size_t)r1 * FH + c] = hi;
        }
    }
}

// ------ Agg layer 1: warp per node, lane owns one float4; dis applied here -
__global__ void k_agg1(const float* __restrict__ b1) {
    int warp = threadIdx.x >> 5, lane = threadIdx.x & 31;
    int node = blockIdx.x * 8 + warp;
    if (node >= NN) return;   // warp-uniform
    const ulonglong2* hv = (const ulonglong2*)g_hs1;
    float dnode = g_dis[node];
    u64 dd;
    DUP2(dd, dnode);
    ulonglong2 self = hv[(size_t)node * 32 + lane];
    u64 aA0 = 0ULL, aA1 = 0ULL, aB0 = 0ULL, aB1 = 0ULL;
    FMA2(aA0, self.x, dd);           // self-loop: dis_i * hs_i
    FMA2(aA1, self.y, dd);
    int s0 = g_rowptr[node], s1 = g_rowptr[node + 1];
    for (int base = s0; base < s1; base += 32) {
        int j = base + lane;
        int sidx = (j < s1) ? __ldcs(&g_ssrc[j]) : 0;
        int cnt = min(32, s1 - base);
        int k = 0;
        for (; k + 1 < cnt; k += 2) {
            int ssA = __shfl_sync(0xffffffffu, sidx, k);
            int ssB = __shfl_sync(0xffffffffu, sidx, k + 1);
            float dA = g_dis[ssA], dB = g_dis[ssB];
            u64 ddA, ddB;
            DUP2(ddA, dA); DUP2(ddB, dB);
            ulonglong2 vA = hv[(size_t)ssA * 32 + lane];
            ulonglong2 vB = hv[(size_t)ssB * 32 + lane];
            FMA2(aA0, vA.x, ddA); FMA2(aA1, vA.y, ddA);
            FMA2(aB0, vB.x, ddB); FMA2(aB1, vB.y, ddB);
        }
        if (k < cnt) {
            int ss = __shfl_sync(0xffffffffu, sidx, k);
            float dC = g_dis[ss];
            u64 ddC;
            DUP2(ddC, dC);
            ulonglong2 v = hv[(size_t)ss * 32 + lane];
            FMA2(aA0, v.x, ddC); FMA2(aA1, v.y, ddC);
        }
    }
    ADD2(aA0, aB0); ADD2(aA1, aB1);
    float a0, a1, a2, a3;
    UNPK2(a0, a1, aA0); UNPK2(a2, a3, aA1);
    float4 b = ((const float4*)b1)[lane];
    float4 o;
    o.x = fmaxf(fmaf(a0, dnode, b.x), 0.f);
    o.y = fmaxf(fmaf(a1, dnode, b.y), 0.f);
    o.z = fmaxf(fmaf(a2, dnode, b.z), 0.f);
    o.w = fmaxf(fmaf(a3, dnode, b.w), 0.f);
    ((float4*)g_a1)[(size_t)node * 32 + lane] = o;
}

// ---------------- GEMM2 (f32x2): hs2[r] = dis[r] * (a1[r] @ W2) -------------
__global__ void k_gemm2(const float* __restrict__ W2) {
    __shared__ float as[64][132];
    __shared__ float ws2[FH * NC];
    int tid = threadIdx.x;
    int n  = tid >> 2;          // 0..63
    int cg = (tid & 3) * 4;     // 0,4,8,12
    int blockRow = blockIdx.x * 64;

    #pragma unroll
    for (int i = 0; i < 8; i++) {
        int t = tid + i * 256;           // 0..2047
        int row = t >> 5;                // 0..63
        int kk = (t & 31) * 4;           // 0..124
        int grow = blockRow + row;
        float4 v = make_float4(0.f, 0.f, 0.f, 0.f);
        if (grow < NN) v = *(const float4*)&g_a1[(size_t)grow * FH + kk];
        as[row][kk + 0] = v.x; as[row][kk + 1] = v.y;
        as[row][kk + 2] = v.z; as[row][kk + 3] = v.w;
    }
    #pragma unroll
    for (int i = 0; i < 8; i++) {
        int t = tid + i * 256;
        ws2[t] = W2[t];
    }
    __syncthreads();

    u64 acc2[2] = {0ULL, 0ULL};   // cols (cg,cg+1),(cg+2,cg+3)
    #pragma unroll 8
    for (int k = 0; k < FH; k++) {
        float av = as[n][k];
        u64 a2;
        DUP2(a2, av);
        ulonglong2 wv = *(const ulonglong2*)&ws2[k * NC + cg];
        FMA2(acc2[0], a2, wv.x);
        FMA2(acc2[1], a2, wv.y);
    }
    int row = blockRow + n;
    if (row < NN) {
        float l0, h0, l1, h1;
        UNPK2(l0, h0, acc2[0]); UNPK2(l1, h1, acc2[1]);
        float dv = g_dis[row];
        float4 o = make_float4(l0 * dv, h0 * dv, l1 * dv, h1 * dv);
        *(float4*)&g_hs2[(size_t)row * NC + cg] = o;
    }
}

// ---------------- Agg layer 2 + bias + log_softmax (quad per node) ---------
__global__ void k_agg2(const float* __restrict__ b2, float* __restrict__ out) {
    int gt = blockIdx.x * blockDim.x + threadIdx.x;
    int node = gt >> 2;
    int q = gt & 3;
    int node_c = (node < NN) ? node : (NN - 1);   // keep all lanes active
    const ulonglong2* hv = (const ulonglong2*)g_hs2;
    ulonglong2 self = hv[(size_t)node_c * 4 + q];
    u64 aA0 = self.x, aA1 = self.y;
    u64 aB0 = 0ULL, aB1 = 0ULL;
    int s0 = g_rowptr[node_c], s1 = g_rowptr[node_c + 1];
    int j = s0;
    for (; j + 1 < s1; j += 2) {
        int sA = __ldcs(&g_ssrc[j]), sB = __ldcs(&g_ssrc[j + 1]);
        ulonglong2 vA = hv[(size_t)sA * 4 + q];
        ulonglong2 vB = hv[(size_t)sB * 4 + q];
        ADD2(aA0, vA.x); ADD2(aA1, vA.y);
        ADD2(aB0, vB.x); ADD2(aB1, vB.y);
    }
    if (j < s1) {
        int s = __ldcs(&g_ssrc[j]);
        ulonglong2 v = hv[(size_t)s * 4 + q];
        ADD2(aA0, v.x); ADD2(aA1, v.y);
    }
    ADD2(aA0, aB0); ADD2(aA1, aB1);
    float a0, a1, a2, a3;
    UNPK2(a0, a1, aA0); UNPK2(a2, a3, aA1);
    float dv = g_dis[node_c];
    float4 b = ((const float4*)b2)[q];
    float v0 = fmaf(a0, dv, b.x);
    float v1 = fmaf(a1, dv, b.y);
    float v2 = fmaf(a2, dv, b.z);
    float v3 = fmaf(a3, dv, b.w);
    float m = fmaxf(fmaxf(v0, v1), fmaxf(v2, v3));
    m = fmaxf(m, __shfl_xor_sync(0xffffffffu, m, 1));
    m = fmaxf(m, __shfl_xor_sync(0xffffffffu, m, 2));
    float e = expf(v0 - m) + expf(v1 - m) + expf(v2 - m) + expf(v3 - m);
    e += __shfl_xor_sync(0xffffffffu, e, 1);
    e += __shfl_xor_sync(0xffffffffu, e, 2);
    float lse = m + logf(e);
    if (node < NN) {
        float4 o = make_float4(v0 - lse, v1 - lse, v2 - lse, v3 - lse);
        ((float4*)out)[(size_t)node * 4 + q] = o;
    }
}

// ---------------- launch (gemm1 stays slot 3 for the ncu window) -----------
extern "C" void kernel_launch(void* const* d_in, const int* in_sizes, int n_in,
                              void* d_out, int out_size) {
    const float* x  = (const float*)d_in[0];
    const void*  ei = d_in[1];
    const float* W1 = (const float*)d_in[2];
    const float* b1 = (const float*)d_in[3];
    const float* W2 = (const float*)d_in[4];
    const float* b2 = (const float*)d_in[5];
    float* out = (float*)d_out;

    k_init<<<(NN + 255) / 256, 256>>>(ei);
    k_hist<<<(NE / 2 + 255) / 256, 256>>>(ei);
    k_scanA<<<NB, 1024>>>();
    k_gemm1<<<(NN + 127) / 128, 256>>>(x, W1);   // slot 3 -> gets profiled
    k_scanB<<<1, 128>>>();
    k_scanC<<<(NN + 255) / 256, 256>>>();
    k_scatter<<<(NE / 2 + 255) / 256, 256>>>(ei);
    k_agg1<<<(NN + 7) / 8, 256>>>(b1);
    k_gemm2<<<(NN + 63) / 64, 256>>>(W2);
    k_agg2<<<(NN * 4 + 255) / 256, 256>>>(b2, out);
}

// round 7
// speedup vs baseline: 1.3864x; 1.0701x over previous
#include <cuda_runtime.h>
#include <cuda_fp16.h>
#include <math.h>
#include <stdint.h>

#define NN 100000
#define NE 1600000
#define FIN 128
#define FH  128
#define NC  16
#define NB  98   // ceil(NN/1024)

typedef unsigned long long u64;

// packed fp32x2 helpers (Blackwell FFMA2 path — exact fp32, 2x fma-pipe rate)
#define FMA2(d, a, b) asm("fma.rn.f32x2 %0, %1, %2, %3;" : "=l"(d) : "l"(a), "l"(b), "l"(d))
#define ADD2(d, v)    asm("add.rn.f32x2 %0, %1, %2;"     : "=l"(d) : "l"(d), "l"(v))
#define DUP2(d, f)    asm("mov.b64 %0, {%1, %1};"        : "=l"(d) : "f"(f))
#define UNPK2(lo, hi, v) asm("mov.b64 {%0, %1}, %2;" : "=f"(lo), "=f"(hi) : "l"(v))

// ---------------- scratch (device globals; no allocation allowed) ----------
__device__ int    g_is64;
__device__ int    g_count[NN];
__device__ int    g_rowptr[NN + 1];
__device__ int    g_woff[NN];
__device__ int    g_bsum[NB];
__device__ int    g_boff[NB];
__device__ int    g_ssrc[NE];
__device__ float  g_dis[NN];
__device__ __half g_hs1h[(size_t)NN * FH];   // UNSCALED x@W1, fp16
__device__ float  g_a1 [(size_t)NN * FH];    // relu(agg1 + b1), fp32
__device__ float  g_hs2[(size_t)NN * NC];    // dis-scaled a1@W2

// ------------- init: zero histogram + detect int64 vs int32 edge_index -----
__global__ void k_init(const void* __restrict__ e) {
    int i = blockIdx.x * blockDim.x + threadIdx.x;
    if (i < NN) g_count[i] = 0;
    if (i == 0) {
        const int* p = (const int*)e;
        int allz = 1;
        #pragma unroll
        for (int k = 0; k < 16; k++)
            if (p[2 * k + 1] != 0) allz = 0;
        g_is64 = allz;   // indices < 100000 -> if int64, every high word is 0
    }
}

__global__ void k_hist(const void* __restrict__ e) {
    int i = blockIdx.x * blockDim.x + threadIdx.x;
    if (i < NE / 2) {
        if (g_is64) {
            longlong2 d = ((const longlong2*)e)[NE / 2 + i];
            atomicAdd(&g_count[(int)d.x], 1);
            atomicAdd(&g_count[(int)d.y], 1);
        } else {
            int2 d = ((const int2*)e)[NE / 2 + i];
            atomicAdd(&g_count[d.x], 1);
            atomicAdd(&g_count[d.y], 1);
        }
    }
}

// ---------------- multi-block exclusive scan of g_count -> g_rowptr --------
__global__ void k_scanA() {
    __shared__ int sw[32];
    int tid = threadIdx.x, lane = tid & 31, w = tid >> 5;
    int idx = blockIdx.x * 1024 + tid;
    int v = (idx < NN) ? g_count[idx] : 0;
    int x = v;
    #pragma unroll
    for (int d = 1; d < 32; d <<= 1) {
        int t = __shfl_up_sync(0xffffffffu, x, d);
        if (lane >= d) x += t;
    }
    if (lane == 31) sw[w] = x;
    __syncthreads();
    if (w == 0) {
        int y = sw[lane];
        #pragma unroll
        for (int d = 1; d < 32; d <<= 1) {
            int t = __shfl_up_sync(0xffffffffu, y, d);
            if (lane >= d) y += t;
        }
        sw[lane] = y;
    }
    __syncthreads();
    int wpre = (w > 0) ? sw[w - 1] : 0;
    if (idx < NN) g_rowptr[idx] = wpre + x - v;
    if (tid == 1023) g_bsum[blockIdx.x] = wpre + x;
}

__global__ void k_scanB() {
    __shared__ int sw[4];
    int tid = threadIdx.x, lane = tid & 31, w = tid >> 5;
    int v = (tid < NB) ? g_bsum[tid] : 0;
    int x = v;
    #pragma unroll
    for (int d = 1; d < 32; d <<= 1) {
        int t = __shfl_up_sync(0xffffffffu, x, d);
        if (lane >= d) x += t;
    }
    if (lane == 31) sw[w] = x;
    __syncthreads();
    int woff = 0;
    for (int i = 0; i < w; i++) woff += sw[i];
    if (tid < NB) g_boff[tid] = woff + x - v;
}

__global__ void k_scanC() {
    int i = blockIdx.x * blockDim.x + threadIdx.x;
    if (i < NN) {
        int rp = g_rowptr[i] + g_boff[i >> 10];
        g_rowptr[i] = rp;
        g_woff[i]   = rp;
        g_dis[i]    = rsqrtf((float)(g_count[i] + 1));  // +1 self loop
        if (i == 0) g_rowptr[NN] = NE;
    }
}

__global__ void k_scatter(const void* __restrict__ e) {
    int i = blockIdx.x * blockDim.x + threadIdx.x;
    if (i < NE / 2) {
        int s0, s1, d0, d1;
        if (g_is64) {
            longlong2 s = ((const longlong2*)e)[i];
            longlong2 d = ((const longlong2*)e)[NE / 2 + i];
            s0 = (int)s.x; s1 = (int)s.y; d0 = (int)d.x; d1 = (int)d.y;
        } else {
            int2 s = ((const int2*)e)[i];
            int2 d = ((const int2*)e)[NE / 2 + i];
            s0 = s.x; s1 = s.y; d0 = d.x; d1 = d.y;
        }
        g_ssrc[atomicAdd(&g_woff[d0], 1)] = s0;
        g_ssrc[atomicAdd(&g_woff[d1], 1)] = s1;
    }
}

// ------ GEMM1 (f32x2): hs1h = fp16(x @ W1), 128x128 tile, 256 thr ----------
// thread tile: 8 rows (4 f32x2 pairs) x 8 cols (stride-16).
// Epilogue: stage fp16 in smem, coalesced uint4 stores.
__global__ void __launch_bounds__(256, 2) k_gemm1(const float* __restrict__ x,
                                                  const float* __restrict__ W) {
    __shared__ char sraw[34816];                    // xs2(16640) + ws(16896); stage(34816)
    u64   (*xs2)[65]  = (u64(*)[65])sraw;           // [k][row-pair]
    float (*ws)[132]  = (float(*)[132])(sraw + 16640);  // [k][col]
    __half* stage     = (__half*)sraw;              // [128][pitch 136]
    int tid = threadIdx.x;
    int tx = tid & 15;               // col set: {tx + 16j}, j=0..7
    int ty = tid >> 4;               // row pairs: ty*4 .. ty*4+3  (8 rows)
    int blockRow = blockIdx.x * 128;

    u64 acc[4][8];
    #pragma unroll
    for (int i = 0; i < 4; i++)
        #pragma unroll
        for (int j = 0; j < 8; j++) acc[i][j] = 0ULL;

    for (int k0 = 0; k0 < FIN; k0 += 32) {
        #pragma unroll
        for (int it = 0; it < 4; it++) {
            int t = tid + it * 256;          // 0..1023
            int r = t >> 3;                  // 0..127
            int kk = (t & 7) * 4;            // 0..28
            int grow = blockRow + r;
            float4 v = make_float4(0.f, 0.f, 0.f, 0.f);
            if (grow < NN) v = *(const float4*)&x[(size_t)grow * FIN + k0 + kk];
            int rp = r >> 1, h = r & 1;
            ((float*)&xs2[kk + 0][rp])[h] = v.x;
            ((float*)&xs2[kk + 1][rp])[h] = v.y;
            ((float*)&xs2[kk + 2][rp])[h] = v.z;
            ((float*)&xs2[kk + 3][rp])[h] = v.w;
        }
        #pragma unroll
        for (int it = 0; it < 4; it++) {
            int t = tid + it * 256;          // 0..1023
            int kk = t >> 5;                 // 0..31
            int c = (t & 31) * 4;            // 0..124
            *(float4*)&ws[kk][c] = *(const float4*)&W[(size_t)(k0 + kk) * FH + c];
        }
        __syncthreads();
        #pragma unroll 8
        for (int k = 0; k < 32; k++) {
            u64 a[4];
            #pragma unroll
            for (int i = 0; i < 4; i++) a[i] = xs2[k][ty * 4 + i];
            u64 w[8];
            #pragma unroll
            for (int j = 0; j < 8; j++) {
                float wv = ws[k][tx + 16 * j];
                DUP2(w[j], wv);
            }
            #pragma unroll
            for (int i = 0; i < 4; i++)
                #pragma unroll
                for (int j = 0; j < 8; j++)
                    FMA2(acc[i][j], a[i], w[j]);
        }
        __syncthreads();
    }
    // stage fp16
    #pragma unroll
    for (int i = 0; i < 4; i++) {
        int r0 = (ty * 4 + i) * 2, r1 = r0 + 1;
        #pragma unroll
        for (int j = 0; j < 8; j++) {
            float lo, hi;
            UNPK2(lo, hi, acc[i][j]);
            int c = tx + 16 * j;
            stage[r0 * 136 + c] = __float2half_rn(lo);
            stage[r1 * 136 + c] = __float2half_rn(hi);
        }
    }
    __syncthreads();
    // coalesced copy out: 128 rows x 128 halves
    #pragma unroll
    for (int it = 0; it < 8; it++) {
        int t = tid + it * 256;          // 0..2047
        int r = t >> 4;                  // 0..127
        int c = (t & 15) * 8;            // 0..120
        int grow = blockRow + r;
        if (grow < NN)
            *(uint4*)&g_hs1h[(size_t)grow * FH + c] = *(const uint4*)&stage[r * 136 + c];
    }
}

// ------ Agg layer 1: warp per node, lane owns 4 cols (fp16 gather) ---------
__global__ void k_agg1(const float* __restrict__ b1) {
    int warp = threadIdx.x >> 5, lane = threadIdx.x & 31;
    int node = blockIdx.x * 8 + warp;
    if (node >= NN) return;   // warp-uniform
    const uint2* hv = (const uint2*)g_hs1h;   // 32 x 8B per row
    float dnode = g_dis[node];
    u64 dd;
    DUP2(dd, dnode);
    u64 aA0 = 0ULL, aA1 = 0ULL, aB0 = 0ULL, aB1 = 0ULL;
    {
        uint2 raw = hv[(size_t)node * 32 + lane];
        float2 f01 = __half22float2(*(__half2*)&raw.x);
        float2 f23 = __half22float2(*(__half2*)&raw.y);
        FMA2(aA0, *(u64*)&f01, dd);      // self-loop: dis_i * hs_i
        FMA2(aA1, *(u64*)&f23, dd);
    }
    int s0 = g_rowptr[node], s1 = g_rowptr[node + 1];
    for (int base = s0; base < s1; base += 32) {
        int j = base + lane;
        int sidx = (j < s1) ? __ldcs(&g_ssrc[j]) : 0;
        int cnt = min(32, s1 - base);
        int k = 0;
        for (; k + 1 < cnt; k += 2) {
            int ssA = __shfl_sync(0xffffffffu, sidx, k);
            int ssB = __shfl_sync(0xffffffffu, sidx, k + 1);
            float dA = g_dis[ssA], dB = g_dis[ssB];
            u64 ddA, ddB;
            DUP2(ddA, dA); DUP2(ddB, dB);
            uint2 rA = hv[(size_t)ssA * 32 + lane];
            uint2 rB = hv[(size_t)ssB * 32 + lane];
            float2 fA0 = __half22float2(*(__half2*)&rA.x);
            float2 fA1 = __half22float2(*(__half2*)&rA.y);
            float2 fB0 = __half22float2(*(__half2*)&rB.x);
            float2 fB1 = __half22float2(*(__half2*)&rB.y);
            FMA2(aA0, *(u64*)&fA0, ddA); FMA2(aA1, *(u64*)&fA1, ddA);
            FMA2(aB0, *(u64*)&fB0, ddB); FMA2(aB1, *(u64*)&fB1, ddB);
        }
        if (k < cnt) {
            int ss = __shfl_sync(0xffffffffu, sidx, k);
            float dC = g_dis[ss];
            u64 ddC;
            DUP2(ddC, dC);
            uint2 rC = hv[(size_t)ss * 32 + lane];
            float2 fC0 = __half22float2(*(__half2*)&rC.x);
            float2 fC1 = __half22float2(*(__half2*)&rC.y);
            FMA2(aA0, *(u64*)&fC0, ddC); FMA2(aA1, *(u64*)&fC1, ddC);
        }
    }
    ADD2(aA0, aB0); ADD2(aA1, aB1);
    float a0, a1, a2, a3;
    UNPK2(a0, a1, aA0); UNPK2(a2, a3, aA1);
    float4 b = ((const float4*)b1)[lane];
    float4 o;
    o.x = fmaxf(fmaf(a0, dnode, b.x), 0.f);
    o.y = fmaxf(fmaf(a1, dnode, b.y), 0.f);
    o.z = fmaxf(fmaf(a2, dnode, b.z), 0.f);
    o.w = fmaxf(fmaf(a3, dnode, b.w), 0.f);
    ((float4*)g_a1)[(size_t)node * 32 + lane] = o;
}

// ---------------- GEMM2 (f32x2): hs2[r] = dis[r] * (a1[r] @ W2) -------------
__global__ void k_gemm2(const float* __restrict__ W2) {
    __shared__ float as[64][132];
    __shared__ float ws2[FH * NC];
    int tid = threadIdx.x;
    int n  = tid >> 2;
    int cg = (tid & 3) * 4;
    int blockRow = blockIdx.x * 64;

    #pragma unroll
    for (int i = 0; i < 8; i++) {
        int t = tid + i * 256;
        int row = t >> 5;
        int kk = (t & 31) * 4;
        int grow = blockRow + row;
        float4 v = make_float4(0.f, 0.f, 0.f, 0.f);
        if (grow < NN) v = *(const float4*)&g_a1[(size_t)grow * FH + kk];
        as[row][kk + 0] = v.x; as[row][kk + 1] = v.y;
        as[row][kk + 2] = v.z; as[row][kk + 3] = v.w;
    }
    #pragma unroll
    for (int i = 0; i < 8; i++) {
        int t = tid + i * 256;
        ws2[t] = W2[t];
    }
    __syncthreads();

    u64 acc2[2] = {0ULL, 0ULL};
    #pragma unroll 8
    for (int k = 0; k < FH; k++) {
        float av = as[n][k];
        u64 a2;
        DUP2(a2, av);
        ulonglong2 wv = *(const ulonglong2*)&ws2[k * NC + cg];
        FMA2(acc2[0], a2, wv.x);
        FMA2(acc2[1], a2, wv.y);
    }
    int row = blockRow + n;
    if (row < NN) {
        float l0, h0, l1, h1;
        UNPK2(l0, h0, acc2[0]); UNPK2(l1, h1, acc2[1]);
        float dv = g_dis[row];
        float4 o = make_float4(l0 * dv, h0 * dv, l1 * dv, h1 * dv);
        *(float4*)&g_hs2[(size_t)row * NC + cg] = o;
    }
}

// ---------------- Agg layer 2 + bias + log_softmax (quad per node) ---------
__global__ void k_agg2(const float* __restrict__ b2, float* __restrict__ out) {
    int gt = blockIdx.x * blockDim.x + threadIdx.x;
    int node = gt >> 2;
    int q = gt & 3;
    int node_c = (node < NN) ? node : (NN - 1);
    const ulonglong2* hv = (const ulonglong2*)g_hs2;
    ulonglong2 self = hv[(size_t)node_c * 4 + q];
    u64 aA0 = self.x, aA1 = self.y;
    u64 aB0 = 0ULL, aB1 = 0ULL;
    int s0 = g_rowptr[node_c], s1 = g_rowptr[node_c + 1];
    int j = s0;
    for (; j + 1 < s1; j += 2) {
        int sA = __ldcs(&g_ssrc[j]), sB = __ldcs(&g_ssrc[j + 1]);
        ulonglong2 vA = hv[(size_t)sA * 4 + q];
        ulonglong2 vB = hv[(size_t)sB * 4 + q];
        ADD2(aA0, vA.x); ADD2(aA1, vA.y);
        ADD2(aB0, vB.x); ADD2(aB1, vB.y);
    }
    if (j < s1) {
        int s = __ldcs(&g_ssrc[j]);
        ulonglong2 v = hv[(size_t)s * 4 + q];
        ADD2(aA0, v.x); ADD2(aA1, v.y);
    }
    ADD2(aA0, aB0); ADD2(aA1, aB1);
    float a0, a1, a2, a3;
    UNPK2(a0, a1, aA0); UNPK2(a2, a3, aA1);
    float dv = g_dis[node_c];
    float4 b = ((const float4*)b2)[q];
    float v0 = fmaf(a0, dv, b.x);
    float v1 = fmaf(a1, dv, b.y);
    float v2 = fmaf(a2, dv, b.z);
    float v3 = fmaf(a3, dv, b.w);
    float m = fmaxf(fmaxf(v0, v1), fmaxf(v2, v3));
    m = fmaxf(m, __shfl_xor_sync(0xffffffffu, m, 1));
    m = fmaxf(m, __shfl_xor_sync(0xffffffffu, m, 2));
    float e = expf(v0 - m) + expf(v1 - m) + expf(v2 - m) + expf(v3 - m);
    e += __shfl_xor_sync(0xffffffffu, e, 1);
    e += __shfl_xor_sync(0xffffffffu, e, 2);
    float lse = m + logf(e);
    if (node < NN) {
        float4 o = make_float4(v0 - lse, v1 - lse, v2 - lse, v3 - lse);
        ((float4*)out)[(size_t)node * 4 + q] = o;
    }
}

// ---------------- launch: fork CSR build parallel to gemm1 -----------------
extern "C" void kernel_launch(void* const* d_in, const int* in_sizes, int n_in,
                              void* d_out, int out_size) {
    const float* x  = (const float*)d_in[0];
    const void*  ei = d_in[1];
    const float* W1 = (const float*)d_in[2];
    const float* b1 = (const float*)d_in[3];
    const float* W2 = (const float*)d_in[4];
    const float* b2 = (const float*)d_in[5];
    float* out = (float*)d_out;

    cudaStream_t s1;
    cudaStreamCreate(&s1);
    cudaEvent_t eFork, eJoin;
    cudaEventCreateWithFlags(&eFork, cudaEventDisableTiming);
    cudaEventCreateWithFlags(&eJoin, cudaEventDisableTiming);

    // fork: CSR build on side stream
    cudaEventRecord(eFork, 0);
    cudaStreamWaitEvent(s1, eFork, 0);
    k_init<<<(NN + 255) / 256, 256, 0, s1>>>(ei);
    k_hist<<<(NE / 2 + 255) / 256, 256, 0, s1>>>(ei);
    k_scanA<<<NB, 1024, 0, s1>>>();
    k_scanB<<<1, 128, 0, s1>>>();
    k_scanC<<<(NN + 255) / 256, 256, 0, s1>>>();
    k_scatter<<<(NE / 2 + 255) / 256, 256, 0, s1>>>(ei);
    cudaEventRecord(eJoin, s1);

    // main stream: dense GEMM1 (independent of CSR)
    k_gemm1<<<(NN + 127) / 128, 256>>>(x, W1);

    // join, then the dependent chain
    cudaStreamWaitEvent(0, eJoin, 0);
    k_agg1<<<(NN + 7) / 8, 256>>>(b1);
    k_gemm2<<<(NN + 63) / 64, 256>>>(W2);
    k_agg2<<<(NN * 4 + 255) / 256, 256>>>(b2, out);
    // streams/events intentionally not destroyed (may be capture-entangled;
    // host-side objects only, kernel_launch is called a bounded number of times)
}

// round 8
// speedup vs baseline: 1.8991x; 1.3698x over previous
#include <cuda_runtime.h>
#include <cuda_fp16.h>
#include <math.h>
#include <stdint.h>

#define NN 100000
#define NE 1600000
#define FIN 128
#define FH  128
#define NC  16
#define NB  98   // ceil(NN/1024)

typedef unsigned long long u64;

// packed fp32x2 helpers (Blackwell FFMA2 path — exact fp32, 2x fma-pipe rate)
#define FMA2(d, a, b) asm("fma.rn.f32x2 %0, %1, %2, %3;" : "=l"(d) : "l"(a), "l"(b), "l"(d))
#define ADD2(d, v)    asm("add.rn.f32x2 %0, %1, %2;"     : "=l"(d) : "l"(d), "l"(v))
#define DUP2(d, f)    asm("mov.b64 %0, {%1, %1};"        : "=l"(d) : "f"(f))
#define UNPK2(lo, hi, v) asm("mov.b64 {%0, %1}, %2;" : "=f"(lo), "=f"(hi) : "l"(v))

#define LDMX4(r0, r1, r2, r3, a) \
    asm volatile("ldmatrix.sync.aligned.m8n8.x4.shared.b16 {%0,%1,%2,%3}, [%4];" \
        : "=r"(r0), "=r"(r1), "=r"(r2), "=r"(r3) : "r"(a))
#define LDMX4T(r0, r1, r2, r3, a) \
    asm volatile("ldmatrix.sync.aligned.m8n8.x4.trans.shared.b16 {%0,%1,%2,%3}, [%4];" \
        : "=r"(r0), "=r"(r1), "=r"(r2), "=r"(r3) : "r"(a))
#define MMA16816(c, a, b0, b1) \
    asm volatile("mma.sync.aligned.m16n8k16.row.col.f32.f16.f16.f32 " \
        "{%0,%1,%2,%3}, {%4,%5,%6,%7}, {%8,%9}, {%0,%1,%2,%3};" \
        : "+f"((c)[0]), "+f"((c)[1]), "+f"((c)[2]), "+f"((c)[3]) \
        : "r"((a)[0]), "r"((a)[1]), "r"((a)[2]), "r"((a)[3]), "r"(b0), "r"(b1))

__device__ __forceinline__ uint32_t smem_u32(const void* p) {
    uint32_t a;
    asm("{ .reg .u64 t; cvta.to.shared.u64 t, %1; cvt.u32.u64 %0, t; }" : "=r"(a) : "l"(p));
    return a;
}

// ---------------- scratch (device globals; no allocation allowed) ----------
__device__ int    g_is64;
__device__ int    g_count[NN];
__device__ int    g_rowptr[NN + 1];
__device__ int    g_woff[NN];
__device__ int    g_bsum[NB];
__device__ int    g_ssrc[NE];
__device__ float  g_dis[NN];
__device__ __half g_hs1h[(size_t)NN * FH];   // UNSCALED x@W1, fp16
__device__ __half g_a1h [(size_t)NN * FH];   // relu(agg1 + b1), fp16
__device__ __half g_hs2h[(size_t)NN * NC];   // dis-scaled a1@W2, fp16

// ------------- init: zero histogram + detect int64 vs int32 edge_index -----
__global__ void k_init(const void* __restrict__ e) {
    int i = blockIdx.x * blockDim.x + threadIdx.x;
    if (i < NN) g_count[i] = 0;
    if (i == 0) {
        const int* p = (const int*)e;
        int allz = 1;
        #pragma unroll
        for (int k = 0; k < 16; k++)
            if (p[2 * k + 1] != 0) allz = 0;
        g_is64 = allz;
    }
}

__global__ void k_hist(const void* __restrict__ e) {
    int i = blockIdx.x * blockDim.x + threadIdx.x;
    if (i < NE / 2) {
        if (g_is64) {
            longlong2 d = ((const longlong2*)e)[NE / 2 + i];
            atomicAdd(&g_count[(int)d.x], 1);
            atomicAdd(&g_count[(int)d.y], 1);
        } else {
            int2 d = ((const int2*)e)[NE / 2 + i];
            atomicAdd(&g_count[d.x], 1);
            atomicAdd(&g_count[d.y], 1);
        }
    }
}

// ---------------- scanA: per-1024-block exclusive scan ----------------------
__global__ void k_scanA() {
    __shared__ int sw[32];
    int tid = threadIdx.x, lane = tid & 31, w = tid >> 5;
    int idx = blockIdx.x * 1024 + tid;
    int v = (idx < NN) ? g_count[idx] : 0;
    int x = v;
    #pragma unroll
    for (int d = 1; d < 32; d <<= 1) {
        int t = __shfl_up_sync(0xffffffffu, x, d);
        if (lane >= d) x += t;
    }
    if (lane == 31) sw[w] = x;
    __syncthreads();
    if (w == 0) {
        int y = sw[lane];
        #pragma unroll
        for (int d = 1; d < 32; d <<= 1) {
            int t = __shfl_up_sync(0xffffffffu, y, d);
            if (lane >= d) y += t;
        }
        sw[lane] = y;
    }
    __syncthreads();
    int wpre = (w > 0) ? sw[w - 1] : 0;
    if (idx < NN) g_rowptr[idx] = wpre + x - v;
    if (tid == 1023) g_bsum[blockIdx.x] = wpre + x;
}

// ------ scanC: redundant per-block scan of g_bsum + finalize rowptr/dis ----
__global__ void k_scanC() {
    __shared__ int boffS[NB];
    __shared__ int sw[4];
    int tid = threadIdx.x, lane = tid & 31, w = tid >> 5;
    int v = 0, x = 0;
    if (tid < 128) {
        v = (tid < NB) ? g_bsum[tid] : 0;
        x = v;
        #pragma unroll
        for (int d = 1; d < 32; d <<= 1) {
            int t = __shfl_up_sync(0xffffffffu, x, d);
            if (lane >= d) x += t;
        }
        if (lane == 31) sw[w] = x;
    }
    __syncthreads();
    if (tid < NB) {
        int woff = 0;
        for (int i = 0; i < w; i++) woff += sw[i];
        boffS[tid] = woff + x - v;
    }
    __syncthreads();
    int i = blockIdx.x * blockDim.x + tid;
    if (i < NN) {
        int rp = g_rowptr[i] + boffS[i >> 10];
        g_rowptr[i] = rp;
        g_woff[i]   = rp;
        g_dis[i]    = rsqrtf((float)(g_count[i] + 1));
        if (i == 0) g_rowptr[NN] = NE;
    }
}

__global__ void k_scatter(const void* __restrict__ e) {
    int i = blockIdx.x * blockDim.x + threadIdx.x;
    if (i < NE / 2) {
        int s0, s1, d0, d1;
        if (g_is64) {
            longlong2 s = ((const longlong2*)e)[i];
            longlong2 d = ((const longlong2*)e)[NE / 2 + i];
            s0 = (int)s.x; s1 = (int)s.y; d0 = (int)d.x; d1 = (int)d.y;
        } else {
            int2 s = ((const int2*)e)[i];
            int2 d = ((const int2*)e)[NE / 2 + i];
            s0 = s.x; s1 = s.y; d0 = d.x; d1 = d.y;
        }
        g_ssrc[atomicAdd(&g_woff[d0], 1)] = s0;
        g_ssrc[atomicAdd(&g_woff[d1], 1)] = s1;
    }
}

// ------ GEMM1 (mma.sync fp16): hs1h = fp16(x @ W1), 128x128x128 per CTA ----
// 8 warps: 4 (M) x 2 (N); warp tile 32x64; m16n8k16; whole K resident.
#define SP 136   // smem pitch in halves
__global__ void __launch_bounds__(256, 2) k_gemm1(const float* __restrict__ x,
                                                  const float* __restrict__ W) {
    extern __shared__ char smem[];
    __half* As = (__half*)smem;            // [128][SP] x tile
    __half* Ws = (__half*)(smem + 128 * SP * 2);  // [128][SP] W1 (k-major)
    uint32_t sbA = smem_u32(As), sbW = smem_u32(Ws);
    int tid = threadIdx.x, wid = tid >> 5, lane = tid & 31;
    int wr = wid & 3, wc = wid >> 2;       // warp row/col block
    int blockRow = blockIdx.x * 128;

    // load x tile -> fp16
    #pragma unroll
    for (int it = 0; it < 16; it++) {
        int t = tid + it * 256;            // 0..4095
        int r = t >> 5, c4 = (t & 31) * 4;
        int grow = blockRow + r;
        float4 v = make_float4(0.f, 0.f, 0.f, 0.f);
        if (grow < NN) v = *(const float4*)&x[(size_t)grow * FIN + c4];
        __half2 h0 = __floats2half2_rn(v.x, v.y);
        __half2 h1 = __floats2half2_rn(v.z, v.w);
        *(uint2*)&As[r * SP + c4] = make_uint2(*(uint32_t*)&h0, *(uint32_t*)&h1);
    }
    // load W1 -> fp16 (k-major rows)
    #pragma unroll
    for (int it = 0; it < 16; it++) {
        int t = tid + it * 256;
        int k = t >> 5, n4 = (t & 31) * 4;
        float4 v = *(const float4*)&W[(size_t)k * FH + n4];
        __half2 h0 = __floats2half2_rn(v.x, v.y);
        __half2 h1 = __floats2half2_rn(v.z, v.w);
        *(uint2*)&Ws[k * SP + n4] = make_uint2(*(uint32_t*)&h0, *(uint32_t*)&h1);
    }
    __syncthreads();

    float c[2][8][4];
    #pragma unroll
    for (int mt = 0; mt < 2; mt++)
        #pragma unroll
        for (int nt = 0; nt < 8; nt++)
            #pragma unroll
            for (int i = 0; i < 4; i++) c[mt][nt][i] = 0.f;

    int lr = lane & 15, lh = lane >> 4;
    #pragma unroll
    for (int ks = 0; ks < 8; ks++) {
        uint32_t a[2][4];
        #pragma unroll
        for (int mt = 0; mt < 2; mt++) {
            uint32_t ad = sbA + ((wr * 32 + mt * 16 + lr) * SP + ks * 16 + 8 * lh) * 2;
            LDMX4(a[mt][0], a[mt][1], a[mt][2], a[mt][3], ad);
        }
        uint32_t b[4][4];
        #pragma unroll
        for (int np = 0; np < 4; np++) {
            uint32_t bd = sbW + ((ks * 16 + lr) * SP + wc * 64 + np * 16 + 8 * lh) * 2;
            LDMX4T(b[np][0], b[np][1], b[np][2], b[np][3], bd);
        }
        #pragma unroll
        for (int mt = 0; mt < 2; mt++)
            #pragma unroll
            for (int nt = 0; nt < 8; nt++)
                MMA16816(c[mt][nt], a[mt], b[nt >> 1][(nt & 1) * 2], b[nt >> 1][(nt & 1) * 2 + 1]);
    }
    __syncthreads();
    // stage fp16 results (reuse As region)
    __half* stage = As;
    int g = lane >> 2, tc = (lane & 3) * 2;
    #pragma unroll
    for (int mt = 0; mt < 2; mt++)
        #pragma unroll
        for (int nt = 0; nt < 8; nt++) {
            int row = wr * 32 + mt * 16 + g;
            int col = wc * 64 + nt * 8 + tc;
            __half2 lo = __floats2half2_rn(c[mt][nt][0], c[mt][nt][1]);
            __half2 hi = __floats2half2_rn(c[mt][nt][2], c[mt][nt][3]);
            *(__half2*)&stage[row * SP + col] = lo;
            *(__half2*)&stage[(row + 8) * SP + col] = hi;
        }
    __syncthreads();
    #pragma unroll
    for (int it = 0; it < 8; it++) {
        int t = tid + it * 256;            // 0..2047
        int r = t >> 4, c8 = (t & 15) * 8;
        int grow = blockRow + r;
        if (grow < NN)
            *(uint4*)&g_hs1h[(size_t)grow * FH + c8] = *(const uint4*)&stage[r * SP + c8];
    }
}

// ------ Agg layer 1: warp per node, half-warp per edge (16 lanes x 16B) ----
__global__ void k_agg1(const float* __restrict__ b1) {
    int warp = threadIdx.x >> 5, lane = threadIdx.x & 31;
    int node = blockIdx.x * 8 + warp;
    if (node >= NN) return;   // warp-uniform
    int h = lane >> 4, q = lane & 15;
    const uint4* hv = (const uint4*)g_hs1h;   // 16 uint4 per row
    float dnode = g_dis[node];
    u64 a0 = 0ULL, a1 = 0ULL, a2 = 0ULL, a3 = 0ULL;
    {   // self-loop only on half 0
        float ds = (h == 0) ? dnode : 0.f;
        u64 dd;
        DUP2(dd, ds);
        uint4 r = hv[(size_t)node * 16 + q];
        float2 f0 = __half22float2(*(__half2*)&r.x);
        float2 f1 = __half22float2(*(__half2*)&r.y);
        float2 f2 = __half22float2(*(__half2*)&r.z);
        float2 f3 = __half22float2(*(__half2*)&r.w);
        FMA2(a0, *(u64*)&f0, dd); FMA2(a1, *(u64*)&f1, dd);
        FMA2(a2, *(u64*)&f2, dd); FMA2(a3, *(u64*)&f3, dd);
    }
    int s0 = g_rowptr[node], s1 = g_rowptr[node + 1];
    for (int j = s0 + h; j < s1; j += 2) {
        int ss = __ldcs(&g_ssrc[j]);          // 16-lane broadcast
        float d = g_dis[ss];
        u64 dd;
        DUP2(dd, d);
        uint4 r = hv[(size_t)ss * 16 + q];
        float2 f0 = __half22float2(*(__half2*)&r.x);
        float2 f1 = __half22float2(*(__half2*)&r.y);
        float2 f2 = __half22float2(*(__half2*)&r.z);
        float2 f3 = __half22float2(*(__half2*)&r.w);
        FMA2(a0, *(u64*)&f0, dd); FMA2(a1, *(u64*)&f1, dd);
        FMA2(a2, *(u64*)&f2, dd); FMA2(a3, *(u64*)&f3, dd);
    }
    // combine halves
    a0 = a0 + 0;  // keep types happy
    u64 o0 = __shfl_xor_sync(0xffffffffu, a0, 16);
    u64 o1 = __shfl_xor_sync(0xffffffffu, a1, 16);
    u64 o2 = __shfl_xor_sync(0xffffffffu, a2, 16);
    u64 o3 = __shfl_xor_sync(0xffffffffu, a3, 16);
    ADD2(a0, o0); ADD2(a1, o1); ADD2(a2, o2); ADD2(a3, o3);
    if (h == 0) {
        float f[8];
        UNPK2(f[0], f[1], a0); UNPK2(f[2], f[3], a1);
        UNPK2(f[4], f[5], a2); UNPK2(f[6], f[7], a3);
        float4 bA = ((const float4*)b1)[q * 2];
        float4 bB = ((const float4*)b1)[q * 2 + 1];
        float o[8];
        o[0] = fmaxf(fmaf(f[0], dnode, bA.x), 0.f);
        o[1] = fmaxf(fmaf(f[1], dnode, bA.y), 0.f);
        o[2] = fmaxf(fmaf(f[2], dnode, bA.z), 0.f);
        o[3] = fmaxf(fmaf(f[3], dnode, bA.w), 0.f);
        o[4] = fmaxf(fmaf(f[4], dnode, bB.x), 0.f);
        o[5] = fmaxf(fmaf(f[5], dnode, bB.y), 0.f);
        o[6] = fmaxf(fmaf(f[6], dnode, bB.z), 0.f);
        o[7] = fmaxf(fmaf(f[7], dnode, bB.w), 0.f);
        __half2 h0 = __floats2half2_rn(o[0], o[1]);
        __half2 h1 = __floats2half2_rn(o[2], o[3]);
        __half2 h2 = __floats2half2_rn(o[4], o[5]);
        __half2 h3 = __floats2half2_rn(o[6], o[7]);
        uint4 st = make_uint4(*(uint32_t*)&h0, *(uint32_t*)&h1,
                              *(uint32_t*)&h2, *(uint32_t*)&h3);
        ((uint4*)g_a1h)[(size_t)node * 16 + q] = st;
    }
}

// ------- GEMM2 (f32x2): hs2h[r] = fp16(dis[r] * (a1[r] @ W2)) ---------------
__global__ void k_gemm2(const float* __restrict__ W2) {
    __shared__ float as[64][132];
    __shared__ float ws2[FH * NC];
    int tid = threadIdx.x;
    int n  = tid >> 2;
    int cg = (tid & 3) * 4;
    int blockRow = blockIdx.x * 64;

    #pragma unroll
    for (int it = 0; it < 4; it++) {
        int t = tid + it * 256;            // 0..1023
        int row = t >> 4, c8 = (t & 15) * 8;
        int grow = blockRow + row;
        uint4 r = make_uint4(0u, 0u, 0u, 0u);
        if (grow < NN) r = ((const uint4*)g_a1h)[(size_t)grow * 16 + (t & 15)];
        float2 f0 = __half22float2(*(__half2*)&r.x);
        float2 f1 = __half22float2(*(__half2*)&r.y);
        float2 f2 = __half22float2(*(__half2*)&r.z);
        float2 f3 = __half22float2(*(__half2*)&r.w);
        as[row][c8 + 0] = f0.x; as[row][c8 + 1] = f0.y;
        as[row][c8 + 2] = f1.x; as[row][c8 + 3] = f1.y;
        as[row][c8 + 4] = f2.x; as[row][c8 + 5] = f2.y;
        as[row][c8 + 6] = f3.x; as[row][c8 + 7] = f3.y;
    }
    #pragma unroll
    for (int i = 0; i < 8; i++) {
        int t = tid + i * 256;
        ws2[t] = W2[t];
    }
    __syncthreads();

    u64 acc2[2] = {0ULL, 0ULL};
    #pragma unroll 8
    for (int k = 0; k < FH; k++) {
        float av = as[n][k];
        u64 a2;
        DUP2(a2, av);
        ulonglong2 wv = *(const ulonglong2*)&ws2[k * NC + cg];
        FMA2(acc2[0], a2, wv.x);
        FMA2(acc2[1], a2, wv.y);
    }
    int row = blockRow + n;
    if (row < NN) {
        float l0, h0, l1, h1;
        UNPK2(l0, h0, acc2[0]); UNPK2(l1, h1, acc2[1]);
        float dv = g_dis[row];
        __half2 p0 = __floats2half2_rn(l0 * dv, h0 * dv);
        __half2 p1 = __floats2half2_rn(l1 * dv, h1 * dv);
        *(uint2*)&g_hs2h[(size_t)row * NC + cg] = make_uint2(*(uint32_t*)&p0, *(uint32_t*)&p1);
    }
}

// ------- Agg layer 2 + bias + log_softmax (2 lanes per node, fp16 gather) ---
__global__ void k_agg2(const float* __restrict__ b2, float* __restrict__ out) {
    int gt = blockIdx.x * blockDim.x + threadIdx.x;
    int node = gt >> 1;
    int q = gt & 1;
    int node_c = (node < NN) ? node : (NN - 1);
    const uint4* hv = (const uint4*)g_hs2h;   // 2 uint4 per row
    u64 aA0, aA1, aA2, aA3;
    {
        uint4 r = hv[(size_t)node_c * 2 + q];
        float2 f0 = __half22float2(*(__half2*)&r.x);
        float2 f1 = __half22float2(*(__half2*)&r.y);
        float2 f2 = __half22float2(*(__half2*)&r.z);
        float2 f3 = __half22float2(*(__half2*)&r.w);
        aA0 = *(u64*)&f0; aA1 = *(u64*)&f1; aA2 = *(u64*)&f2; aA3 = *(u64*)&f3;
    }
    int s0 = g_rowptr[node_c], s1 = g_rowptr[node_c + 1];
    for (int j = s0; j < s1; j++) {
        int s = __ldcs(&g_ssrc[j]);
        uint4 r = hv[(size_t)s * 2 + q];
        float2 f0 = __half22float2(*(__half2*)&r.x);
        float2 f1 = __half22float2(*(__half2*)&r.y);
        float2 f2 = __half22float2(*(__half2*)&r.z);
        float2 f3 = __half22float2(*(__half2*)&r.w);
        ADD2(aA0, *(u64*)&f0); ADD2(aA1, *(u64*)&f1);
        ADD2(aA2, *(u64*)&f2); ADD2(aA3, *(u64*)&f3);
    }
    float f[8];
    UNPK2(f[0], f[1], aA0); UNPK2(f[2], f[3], aA1);
    UNPK2(f[4], f[5], aA2); UNPK2(f[6], f[7], aA3);
    float dv = g_dis[node_c];
    float4 bA = ((const float4*)b2)[q * 2];
    float4 bB = ((const float4*)b2)[q * 2 + 1];
    float v[8];
    v[0] = fmaf(f[0], dv, bA.x); v[1] = fmaf(f[1], dv, bA.y);
    v[2] = fmaf(f[2], dv, bA.z); v[3] = fmaf(f[3], dv, bA.w);
    v[4] = fmaf(f[4], dv, bB.x); v[5] = fmaf(f[5], dv, bB.y);
    v[6] = fmaf(f[6], dv, bB.z); v[7] = fmaf(f[7], dv, bB.w);
    float m = v[0];
    #pragma unroll
    for (int i = 1; i < 8; i++) m = fmaxf(m, v[i]);
    m = fmaxf(m, __shfl_xor_sync(0xffffffffu, m, 1));
    float e = 0.f;
    #pragma unroll
    for (int i = 0; i < 8; i++) e += expf(v[i] - m);
    e += __shfl_xor_sync(0xffffffffu, e, 1);
    float lse = m + logf(e);
    if (node < NN) {
        float4 o0 = make_float4(v[0] - lse, v[1] - lse, v[2] - lse, v[3] - lse);
        float4 o1 = make_float4(v[4] - lse, v[5] - lse, v[6] - lse, v[7] - lse);
        ((float4*)out)[(size_t)node * 4 + q * 2]     = o0;
        ((float4*)out)[(size_t)node * 4 + q * 2 + 1] = o1;
    }
}

// ---------------- launch: fork CSR build parallel to gemm1 -----------------
extern "C" void kernel_launch(void* const* d_in, const int* in_sizes, int n_in,
                              void* d_out, int out_size) {
    const float* x  = (const float*)d_in[0];
    const void*  ei = d_in[1];
    const float* W1 = (const float*)d_in[2];
    const float* b1 = (const float*)d_in[3];
    const float* W2 = (const float*)d_in[4];
    const float* b2 = (const float*)d_in[5];
    float* out = (float*)d_out;

    const int GEMM1_SMEM = 2 * 128 * SP * 2;   // 69632
    cudaFuncSetAttribute(k_gemm1, cudaFuncAttributeMaxDynamicSharedMemorySize, GEMM1_SMEM);

    cudaStream_t s1;
    cudaStreamCreate(&s1);
    cudaEvent_t eFork, eJoin;
    cudaEventCreateWithFlags(&eFork, cudaEventDisableTiming);
    cudaEventCreateWithFlags(&eJoin, cudaEventDisableTiming);

    cudaEventRecord(eFork, 0);
    cudaStreamWaitEvent(s1, eFork, 0);
    k_init<<<(NN + 255) / 256, 256, 0, s1>>>(ei);
    k_hist<<<(NE / 2 + 255) / 256, 256, 0, s1>>>(ei);
    k_scanA<<<NB, 1024, 0, s1>>>();
    k_gemm1<<<(NN + 127) / 128, 256, GEMM1_SMEM>>>(x, W1);  // 4th submit -> profiled
    k_scanC<<<(NN + 255) / 256, 256, 0, s1>>>();
    k_scatter<<<(NE / 2 + 255) / 256, 256, 0, s1>>>(ei);
    cudaEventRecord(eJoin, s1);

    cudaStreamWaitEvent(0, eJoin, 0);
    k_agg1<<<(NN + 7) / 8, 256>>>(b1);
    k_gemm2<<<(NN + 63) / 64, 256>>>(W2);
    k_agg2<<<(NN * 2 + 255) / 256, 256>>>(b2, out);
    // streams/events intentionally not destroyed (host-side objects only)
}